// round 1
// baseline (speedup 1.0000x reference)
#include <cuda_runtime.h>
#include <math.h>

// Problem constants
#define Bb   4
#define Tt   2048
#define Cc   1024
#define Hh   16
#define HSd  64
#define Mm   (Bb * Tt)      // 8192
#define NQKV (3 * Cc)       // 3072

// Scratch (static device globals: allocation rules forbid cudaMalloc)
__device__ float g_qkv[(size_t)Mm * NQKV];    // [B*T, 3C] : q|k|v
__device__ float g_attn[(size_t)Mm * Cc];     // [B*T, C]  : attention out

// ---------------------------------------------------------------------------
// SGEMM: C = A[MxK] @ B[KxN] (+ bias). 128x128 tile, BK=16, 256 thr, 8x8/thr.
// All dims are multiples of tile sizes for this problem -> no bounds checks.
// ---------------------------------------------------------------------------
template <bool HAS_BIAS>
__global__ __launch_bounds__(256)
void sgemm_kernel(const float* __restrict__ A, const float* __restrict__ B,
                  const float* __restrict__ bias, float* __restrict__ C,
                  int M, int N, int K)
{
    __shared__ float As[16][132];   // A tile, transposed [k][m], padded
    __shared__ float Bs[16][132];   // B tile [k][n], padded

    const int tid = threadIdx.x;
    const int m0 = blockIdx.y * 128;
    const int n0 = blockIdx.x * 128;
    const int ty = tid >> 4;          // 0..15
    const int tx = tid & 15;          // 0..15
    const int aRow = tid >> 2;        // 0..63
    const int aCol = (tid & 3) << 2;  // 0,4,8,12
    const int bRow = tid >> 5;        // 0..7
    const int bCol = (tid & 31) << 2; // 0..124

    float acc[8][8];
    #pragma unroll
    for (int i = 0; i < 8; i++)
        #pragma unroll
        for (int j = 0; j < 8; j++) acc[i][j] = 0.0f;

    const float* Abase = A + (size_t)m0 * K;

    for (int k0 = 0; k0 < K; k0 += 16) {
        float4 a0 = *(const float4*)(Abase + (size_t)aRow        * K + k0 + aCol);
        float4 a1 = *(const float4*)(Abase + (size_t)(aRow + 64) * K + k0 + aCol);
        float4 b0 = *(const float4*)(B + (size_t)(k0 + bRow)     * N + n0 + bCol);
        float4 b1 = *(const float4*)(B + (size_t)(k0 + bRow + 8) * N + n0 + bCol);

        As[aCol + 0][aRow] = a0.x;  As[aCol + 1][aRow] = a0.y;
        As[aCol + 2][aRow] = a0.z;  As[aCol + 3][aRow] = a0.w;
        As[aCol + 0][aRow + 64] = a1.x;  As[aCol + 1][aRow + 64] = a1.y;
        As[aCol + 2][aRow + 64] = a1.z;  As[aCol + 3][aRow + 64] = a1.w;
        *(float4*)&Bs[bRow][bCol]     = b0;
        *(float4*)&Bs[bRow + 8][bCol] = b1;
        __syncthreads();

        #pragma unroll
        for (int kk = 0; kk < 16; kk++) {
            float ra[8], rb[8];
            *(float4*)&ra[0] = *(const float4*)&As[kk][ty * 8];
            *(float4*)&ra[4] = *(const float4*)&As[kk][ty * 8 + 4];
            *(float4*)&rb[0] = *(const float4*)&Bs[kk][tx * 8];
            *(float4*)&rb[4] = *(const float4*)&Bs[kk][tx * 8 + 4];
            #pragma unroll
            for (int i = 0; i < 8; i++)
                #pragma unroll
                for (int j = 0; j < 8; j++)
                    acc[i][j] = fmaf(ra[i], rb[j], acc[i][j]);
        }
        __syncthreads();
    }

    #pragma unroll
    for (int i = 0; i < 8; i++) {
        size_t rowoff = (size_t)(m0 + ty * 8 + i) * N + n0 + tx * 8;
        #pragma unroll
        for (int j = 0; j < 8; j += 4) {
            float4 v;
            v.x = acc[i][j + 0]; v.y = acc[i][j + 1];
            v.z = acc[i][j + 2]; v.w = acc[i][j + 3];
            if (HAS_BIAS) {
                int n = n0 + tx * 8 + j;
                v.x += bias[n + 0]; v.y += bias[n + 1];
                v.z += bias[n + 2]; v.w += bias[n + 3];
            }
            *(float4*)(C + rowoff + j) = v;
        }
    }
}

// ---------------------------------------------------------------------------
// Flash attention (fp32, causal). One thread per query row. Block = 256 rows
// of one (b,h). K/V tiles of 64 keys staged in shared; online softmax in
// 8-key chunks. Heavy q-chunks launched first (reversed blockIdx.x).
// ---------------------------------------------------------------------------
__global__ __launch_bounds__(256)
void flash_attn_kernel(const float* __restrict__ qkv, float* __restrict__ out)
{
    __shared__ float Ks[64 * 64];
    __shared__ float Vs[64 * 64];

    const int bh = blockIdx.y;             // 0..B*H-1
    const int b  = bh / Hh;
    const int h  = bh % Hh;
    const int qchunk = gridDim.x - 1 - blockIdx.x;   // heavy chunks first
    const int tid = threadIdx.x;
    const int t = qchunk * 256 + tid;      // query row in [0, T)

    const float scale = 0.125f;            // 1/sqrt(64)

    // Load this thread's query row (pre-scaled)
    float q[HSd];
    const float* qptr = qkv + ((size_t)(b * Tt + t)) * NQKV + h * HSd;
    #pragma unroll
    for (int d = 0; d < HSd; d += 4) {
        float4 v4 = *(const float4*)(qptr + d);
        q[d + 0] = v4.x * scale; q[d + 1] = v4.y * scale;
        q[d + 2] = v4.z * scale; q[d + 3] = v4.w * scale;
    }

    float acc[HSd];
    #pragma unroll
    for (int d = 0; d < HSd; d++) acc[d] = 0.0f;
    float m = -3.4e38f, l = 0.0f;

    const float* kbase = qkv + ((size_t)b * Tt) * NQKV + Cc + h * HSd;
    const float* vbase = kbase + Cc;

    const int ntiles = (qchunk * 256 + 255) / 64 + 1;   // keys 0 .. q0+255

    for (int kt = 0; kt < ntiles; kt++) {
        __syncthreads();
        // Cooperative, coalesced load of 64 K rows + 64 V rows (64 floats each)
        #pragma unroll
        for (int i = 0; i < 4; i++) {
            int idx = i * 256 + tid;          // float4 index 0..1023
            int row = idx >> 4;
            int col = (idx & 15) << 2;
            *(float4*)&Ks[row * 64 + col] =
                *(const float4*)(kbase + (size_t)(kt * 64 + row) * NQKV + col);
            *(float4*)&Vs[row * 64 + col] =
                *(const float4*)(vbase + (size_t)(kt * 64 + row) * NQKV + col);
        }
        __syncthreads();

        #pragma unroll 1
        for (int c = 0; c < 64; c += 8) {
            float s[8];
            #pragma unroll
            for (int j = 0; j < 8; j++) {
                const float* kr = &Ks[(c + j) * 64];
                float sum = 0.0f;
                #pragma unroll
                for (int d = 0; d < HSd; d++) sum = fmaf(q[d], kr[d], sum);
                int kg = kt * 64 + c + j;
                s[j] = (kg <= t) ? sum : -3.4e38f;
            }
            float cmax = s[0];
            #pragma unroll
            for (int j = 1; j < 8; j++) cmax = fmaxf(cmax, s[j]);
            float mnew = fmaxf(m, cmax);
            float corr = __expf(m - mnew);
            float p[8];
            float psum = 0.0f;
            #pragma unroll
            for (int j = 0; j < 8; j++) { p[j] = __expf(s[j] - mnew); psum += p[j]; }
            l = l * corr + psum;
            m = mnew;
            #pragma unroll
            for (int d = 0; d < HSd; d++) acc[d] *= corr;
            #pragma unroll
            for (int j = 0; j < 8; j++) {
                const float* vr = &Vs[(c + j) * 64];
                float pj = p[j];
                #pragma unroll
                for (int d = 0; d < HSd; d++) acc[d] = fmaf(pj, vr[d], acc[d]);
            }
        }
    }

    float inv = 1.0f / l;
    float* optr = out + ((size_t)(b * Tt + t)) * Cc + h * HSd;
    #pragma unroll
    for (int d = 0; d < HSd; d += 4) {
        float4 v;
        v.x = acc[d + 0] * inv; v.y = acc[d + 1] * inv;
        v.z = acc[d + 2] * inv; v.w = acc[d + 3] * inv;
        *(float4*)(optr + d) = v;
    }
}

// ---------------------------------------------------------------------------
extern "C" void kernel_launch(void* const* d_in, const int* in_sizes, int n_in,
                              void* d_out, int out_size)
{
    const float* x     = (const float*)d_in[0];   // [B,T,C]
    const float* Wqkv  = (const float*)d_in[1];   // [C,3C]
    const float* Wproj = (const float*)d_in[2];   // [C,C]
    const float* bproj = (const float*)d_in[3];   // [C]
    float* out = (float*)d_out;                   // [B,T,C]

    float *qkv, *attn;
    cudaGetSymbolAddress((void**)&qkv,  g_qkv);
    cudaGetSymbolAddress((void**)&attn, g_attn);

    dim3 blk(256);
    // 1) QKV projection: [8192,1024] @ [1024,3072]
    sgemm_kernel<false><<<dim3(NQKV / 128, Mm / 128), blk>>>(x, Wqkv, nullptr, qkv,
                                                             Mm, NQKV, Cc);
    // 2) Causal flash attention -> [B,T,C] layout
    flash_attn_kernel<<<dim3(Tt / 256, Bb * Hh), blk>>>(qkv, attn);
    // 3) Output projection + bias: [8192,1024] @ [1024,1024]
    sgemm_kernel<true><<<dim3(Cc / 128, Mm / 128), blk>>>(attn, Wproj, bproj, out,
                                                          Mm, Cc, Cc);
}

// round 4
// speedup vs baseline: 1.2709x; 1.2709x over previous
#include <cuda_runtime.h>
#include <math.h>
#include <stdint.h>

// Problem constants
#define Bb   4
#define Tt   2048
#define Cc   1024
#define Hh   16
#define HSd  64
#define Mm   (Bb * Tt)      // 8192
#define NQKV (3 * Cc)       // 3072

// Scratch (static device globals: allocation rules forbid cudaMalloc)
__device__ float g_qkv[(size_t)Mm * NQKV];    // [B*T, 3C] : q|k|v
__device__ float g_attn[(size_t)Mm * Cc];     // [B*T, C]  : attention out

// ---------------------------------------------------------------------------
// tf32 helpers
// ---------------------------------------------------------------------------
static __device__ __forceinline__ uint32_t f2tf32(float x) {
    uint32_t y;
    asm("cvt.rna.tf32.f32 %0, %1;" : "=r"(y) : "f"(x));
    return y;
}

static __device__ __forceinline__ void mma_tf32(float c[4], const uint32_t a[4],
                                                const uint32_t b[2]) {
    asm volatile(
        "mma.sync.aligned.m16n8k8.row.col.f32.tf32.tf32.f32 "
        "{%0,%1,%2,%3}, {%4,%5,%6,%7}, {%8,%9}, {%0,%1,%2,%3};\n"
        : "+f"(c[0]), "+f"(c[1]), "+f"(c[2]), "+f"(c[3])
        : "r"(a[0]), "r"(a[1]), "r"(a[2]), "r"(a[3]), "r"(b[0]), "r"(b[1]));
}

// ---------------------------------------------------------------------------
// tf32 tensor-core GEMM: C = A[MxK] @ B[KxN] (+ bias).
// 128x128 tile, BK=16, 256 threads (8 warps, 4x2), warp tile 32x64.
// Double-buffered smem. A layout: [row][24] with k-pair permutation
//   word(r,k) = r*24 + (k>>3)*8 + 2*(k&3) + ((k&7)>>2)
// -> one conflict-free LDS.64 per A fragment half. B layout: [k][128] row-major
// -> B fragments are broadcast LDS.32, conflict-free.
// All dims multiples of tile sizes -> no bounds checks.
// ---------------------------------------------------------------------------
#define SA 24

template <bool HAS_BIAS>
__global__ __launch_bounds__(256, 2)
void tgemm_kernel(const float* __restrict__ A, const float* __restrict__ B,
                  const float* __restrict__ bias, float* __restrict__ C,
                  int M, int N, int K)
{
    __shared__ float As[2][128 * SA];
    __shared__ float Bs[2][16 * 128];

    const int tid  = threadIdx.x;
    const int lane = tid & 31;
    const int warp = tid >> 5;
    const int m0 = blockIdx.y * 128;
    const int n0 = blockIdx.x * 128;
    const int wr = (warp & 3) * 32;   // warp m offset in tile
    const int wn = (warp >> 2) * 64;  // warp n offset in tile
    const int r0 = lane >> 2;         // 0..7
    const int c0 = lane & 3;          // 0..3

    // Global load assignments
    const int aRow  = tid >> 2;         // 0..63 (+64)
    const int aCol4 = (tid & 3) * 4;    // k offset 0,4,8,12
    const int bKr   = tid >> 5;         // 0..7 (+8)
    const int bN4   = (tid & 31) * 4;   // n offset 0..124

    float c[2][8][4];
    #pragma unroll
    for (int mi = 0; mi < 2; mi++)
        #pragma unroll
        for (int ni = 0; ni < 8; ni++)
            #pragma unroll
            for (int j = 0; j < 4; j++) c[mi][ni][j] = 0.0f;

    const float* Abase = A + (size_t)m0 * K;
    const float* Bbase = B + n0;

    const int nk = K / 16;

    // helper lambdas (inlined)
    auto ldgA = [&](int kb, float4& a0, float4& a1) {
        a0 = *(const float4*)(Abase + (size_t)aRow        * K + kb * 16 + aCol4);
        a1 = *(const float4*)(Abase + (size_t)(aRow + 64) * K + kb * 16 + aCol4);
    };
    auto ldgB = [&](int kb, float4& b0, float4& b1) {
        b0 = *(const float4*)(Bbase + (size_t)(kb * 16 + bKr)     * N + bN4);
        b1 = *(const float4*)(Bbase + (size_t)(kb * 16 + bKr + 8) * N + bN4);
    };
    auto stsA = [&](int buf, float4 v, int row) {
        float* dst = &As[buf][row * SA];
        #pragma unroll
        for (int j = 0; j < 4; j++) {
            int k = aCol4 + j;
            int word = ((k >> 3) << 3) + 2 * (k & 3) + ((k & 7) >> 2);
            float x = (j == 0) ? v.x : (j == 1) ? v.y : (j == 2) ? v.z : v.w;
            dst[word] = __uint_as_float(f2tf32(x));
        }
    };
    auto stsB = [&](int buf, float4 v, int krow) {
        float4 w;
        w.x = __uint_as_float(f2tf32(v.x));
        w.y = __uint_as_float(f2tf32(v.y));
        w.z = __uint_as_float(f2tf32(v.z));
        w.w = __uint_as_float(f2tf32(v.w));
        *(float4*)&Bs[buf][krow * 128 + bN4] = w;
    };

    // Prologue: stage block 0
    {
        float4 a0, a1, b0, b1;
        ldgA(0, a0, a1);
        ldgB(0, b0, b1);
        stsA(0, a0, aRow);
        stsA(0, a1, aRow + 64);
        stsB(0, b0, bKr);
        stsB(0, b1, bKr + 8);
    }
    __syncthreads();

    float4 pa0, pa1, pb0, pb1;
    for (int kb = 0; kb < nk; kb++) {
        const int buf = kb & 1;
        const bool more = (kb + 1) < nk;
        if (more) { ldgA(kb + 1, pa0, pa1); ldgB(kb + 1, pb0, pb1); }

        // Compute on staged block
        #pragma unroll
        for (int g = 0; g < 2; g++) {
            uint32_t a[2][4], b[8][2];
            #pragma unroll
            for (int mi = 0; mi < 2; mi++) {
                const uint2 lo = *(const uint2*)&As[buf][(wr + mi * 16 + r0)     * SA + g * 8 + 2 * c0];
                const uint2 hi = *(const uint2*)&As[buf][(wr + mi * 16 + 8 + r0) * SA + g * 8 + 2 * c0];
                a[mi][0] = lo.x; a[mi][1] = hi.x; a[mi][2] = lo.y; a[mi][3] = hi.y;
            }
            #pragma unroll
            for (int ni = 0; ni < 8; ni++) {
                b[ni][0] = __float_as_uint(Bs[buf][(g * 8 + c0)     * 128 + wn + ni * 8 + r0]);
                b[ni][1] = __float_as_uint(Bs[buf][(g * 8 + c0 + 4) * 128 + wn + ni * 8 + r0]);
            }
            #pragma unroll
            for (int mi = 0; mi < 2; mi++)
                #pragma unroll
                for (int ni = 0; ni < 8; ni++)
                    mma_tf32(c[mi][ni], a[mi], b[ni]);
        }

        if (more) {
            const int nbuf = buf ^ 1;
            stsA(nbuf, pa0, aRow);
            stsA(nbuf, pa1, aRow + 64);
            stsB(nbuf, pb0, bKr);
            stsB(nbuf, pb1, bKr + 8);
            __syncthreads();
        }
    }

    // Epilogue: c[mi][ni] = {(r0, 2c0), (r0, 2c0+1), (r0+8, 2c0), (r0+8, 2c0+1)}
    #pragma unroll
    for (int mi = 0; mi < 2; mi++) {
        #pragma unroll
        for (int ni = 0; ni < 8; ni++) {
            int row = m0 + wr + mi * 16 + r0;
            int col = n0 + wn + ni * 8 + 2 * c0;
            float2 v0, v1;
            v0.x = c[mi][ni][0]; v0.y = c[mi][ni][1];
            v1.x = c[mi][ni][2]; v1.y = c[mi][ni][3];
            if (HAS_BIAS) {
                float bx = bias[col], by = bias[col + 1];
                v0.x += bx; v0.y += by;
                v1.x += bx; v1.y += by;
            }
            *(float2*)(C + (size_t)row * N + col)       = v0;
            *(float2*)(C + (size_t)(row + 8) * N + col) = v1;
        }
    }
}

// ---------------------------------------------------------------------------
// Flash attention (fp32, causal). One thread per query row. Block = 256 rows
// of one (b,h). K/V tiles of 64 keys staged in shared; online softmax in
// 8-key chunks. Heavy q-chunks launched first (reversed blockIdx.x).
// ---------------------------------------------------------------------------
__global__ __launch_bounds__(256)
void flash_attn_kernel(const float* __restrict__ qkv, float* __restrict__ out)
{
    __shared__ float Ks[64 * 64];
    __shared__ float Vs[64 * 64];

    const int bh = blockIdx.y;             // 0..B*H-1
    const int b  = bh / Hh;
    const int h  = bh % Hh;
    const int qchunk = gridDim.x - 1 - blockIdx.x;   // heavy chunks first
    const int tid = threadIdx.x;
    const int t = qchunk * 256 + tid;      // query row in [0, T)

    const float scale = 0.125f;            // 1/sqrt(64)

    float q[HSd];
    const float* qptr = qkv + ((size_t)(b * Tt + t)) * NQKV + h * HSd;
    #pragma unroll
    for (int d = 0; d < HSd; d += 4) {
        float4 v4 = *(const float4*)(qptr + d);
        q[d + 0] = v4.x * scale; q[d + 1] = v4.y * scale;
        q[d + 2] = v4.z * scale; q[d + 3] = v4.w * scale;
    }

    float acc[HSd];
    #pragma unroll
    for (int d = 0; d < HSd; d++) acc[d] = 0.0f;
    float m = -3.4e38f, l = 0.0f;

    const float* kbase = qkv + ((size_t)b * Tt) * NQKV + Cc + h * HSd;
    const float* vbase = kbase + Cc;

    const int ntiles = (qchunk * 256 + 255) / 64 + 1;   // keys 0 .. q0+255

    for (int kt = 0; kt < ntiles; kt++) {
        __syncthreads();
        #pragma unroll
        for (int i = 0; i < 4; i++) {
            int idx = i * 256 + tid;
            int row = idx >> 4;
            int col = (idx & 15) << 2;
            *(float4*)&Ks[row * 64 + col] =
                *(const float4*)(kbase + (size_t)(kt * 64 + row) * NQKV + col);
            *(float4*)&Vs[row * 64 + col] =
                *(const float4*)(vbase + (size_t)(kt * 64 + row) * NQKV + col);
        }
        __syncthreads();

        #pragma unroll 1
        for (int c = 0; c < 64; c += 8) {
            float s[8];
            #pragma unroll
            for (int j = 0; j < 8; j++) {
                const float* kr = &Ks[(c + j) * 64];
                float sum = 0.0f;
                #pragma unroll
                for (int d = 0; d < HSd; d++) sum = fmaf(q[d], kr[d], sum);
                int kg = kt * 64 + c + j;
                s[j] = (kg <= t) ? sum : -3.4e38f;
            }
            float cmax = s[0];
            #pragma unroll
            for (int j = 1; j < 8; j++) cmax = fmaxf(cmax, s[j]);
            float mnew = fmaxf(m, cmax);
            float corr = __expf(m - mnew);
            float p[8];
            float psum = 0.0f;
            #pragma unroll
            for (int j = 0; j < 8; j++) { p[j] = __expf(s[j] - mnew); psum += p[j]; }
            l = l * corr + psum;
            m = mnew;
            #pragma unroll
            for (int d = 0; d < HSd; d++) acc[d] *= corr;
            #pragma unroll
            for (int j = 0; j < 8; j++) {
                const float* vr = &Vs[(c + j) * 64];
                float pj = p[j];
                #pragma unroll
                for (int d = 0; d < HSd; d++) acc[d] = fmaf(pj, vr[d], acc[d]);
            }
        }
    }

    float inv = 1.0f / l;
    float* optr = out + ((size_t)(b * Tt + t)) * Cc + h * HSd;
    #pragma unroll
    for (int d = 0; d < HSd; d += 4) {
        float4 v;
        v.x = acc[d + 0] * inv; v.y = acc[d + 1] * inv;
        v.z = acc[d + 2] * inv; v.w = acc[d + 3] * inv;
        *(float4*)(optr + d) = v;
    }
}

// ---------------------------------------------------------------------------
extern "C" void kernel_launch(void* const* d_in, const int* in_sizes, int n_in,
                              void* d_out, int out_size)
{
    const float* x     = (const float*)d_in[0];   // [B,T,C]
    const float* Wqkv  = (const float*)d_in[1];   // [C,3C]
    const float* Wproj = (const float*)d_in[2];   // [C,C]
    const float* bproj = (const float*)d_in[3];   // [C]
    float* out = (float*)d_out;                   // [B,T,C]

    float *qkv, *attn;
    cudaGetSymbolAddress((void**)&qkv,  g_qkv);
    cudaGetSymbolAddress((void**)&attn, g_attn);

    dim3 blk(256);
    // 1) QKV projection: [8192,1024] @ [1024,3072] (tf32 tensor cores)
    tgemm_kernel<false><<<dim3(NQKV / 128, Mm / 128), blk>>>(x, Wqkv, nullptr, qkv,
                                                             Mm, NQKV, Cc);
    // 2) Causal flash attention -> [B,T,C] layout
    flash_attn_kernel<<<dim3(Tt / 256, Bb * Hh), blk>>>(qkv, attn);
    // 3) Output projection + bias: [8192,1024] @ [1024,1024] (tf32 tensor cores)
    tgemm_kernel<true><<<dim3(Cc / 128, Mm / 128), blk>>>(attn, Wproj, bproj, out,
                                                          Mm, Cc, Cc);
}

// round 5
// speedup vs baseline: 2.4043x; 1.8919x over previous
#include <cuda_runtime.h>
#include <math.h>
#include <stdint.h>

// Problem constants
#define Bb   4
#define Tt   2048
#define Cc   1024
#define Hh   16
#define HSd  64
#define Mm   (Bb * Tt)      // 8192
#define NQKV (3 * Cc)       // 3072

// Scratch (static device globals: allocation rules forbid cudaMalloc)
__device__ float g_qkv[(size_t)Mm * NQKV];    // [B*T, 3C] : q|k|v
__device__ float g_attn[(size_t)Mm * Cc];     // [B*T, C]  : attention out

// ---------------------------------------------------------------------------
// tf32 helpers
// ---------------------------------------------------------------------------
static __device__ __forceinline__ uint32_t f2tf32(float x) {
    uint32_t y;
    asm("cvt.rna.tf32.f32 %0, %1;" : "=r"(y) : "f"(x));
    return y;
}

static __device__ __forceinline__ float exp2fast(float x) {
    float y;
    asm("ex2.approx.f32 %0, %1;" : "=f"(y) : "f"(x));
    return y;
}

static __device__ __forceinline__ void mma_tf32(float c[4], const uint32_t a[4],
                                                const uint32_t b[2]) {
    asm volatile(
        "mma.sync.aligned.m16n8k8.row.col.f32.tf32.tf32.f32 "
        "{%0,%1,%2,%3}, {%4,%5,%6,%7}, {%8,%9}, {%0,%1,%2,%3};\n"
        : "+f"(c[0]), "+f"(c[1]), "+f"(c[2]), "+f"(c[3])
        : "r"(a[0]), "r"(a[1]), "r"(a[2]), "r"(a[3]), "r"(b[0]), "r"(b[1]));
}

// ---------------------------------------------------------------------------
// tf32 tensor-core GEMM with split-A (2xTF32 on activations):
//   C = (Ahi + Alo) @ tf32(B) (+ bias)
// 128x128 tile, BK=16, 256 threads (8 warps, 4x2), warp tile 32x64.
// Double-buffered smem. A layout: [row][24] with k-pair permutation
//   word(r,k) = (k>>3)*8 + 2*(k&3) + ((k&7)>>2)
// -> one conflict-free LDS.64 per A fragment half.
// B layout: [k][128] with XOR swizzle col ^= 8*(k&3) -> B fragment reads
// are conflict-free LDS.32.
// Dynamic smem: As(2*3072) | Alo(2*3072) | Bs(2*2048) floats = 64KB.
// ---------------------------------------------------------------------------
template <bool HAS_BIAS>
__global__ __launch_bounds__(256, 2)
void tgemm_kernel(const float* __restrict__ A, const float* __restrict__ B,
                  const float* __restrict__ bias, float* __restrict__ C,
                  int M, int N, int K)
{
    extern __shared__ float smg[];
    float* Ash = smg;              // [2][128*24]
    float* Alo = smg + 6144;       // [2][128*24]
    float* Bsm = smg + 12288;      // [2][16*128]

    const int tid  = threadIdx.x;
    const int lane = tid & 31;
    const int warp = tid >> 5;
    const int m0 = blockIdx.y * 128;
    const int n0 = blockIdx.x * 128;
    const int wr = (warp & 3) * 32;   // warp m offset
    const int wn = (warp >> 2) * 64;  // warp n offset
    const int r0 = lane >> 2;         // 0..7
    const int c0 = lane & 3;          // 0..3
    const int xr = 8 * c0;            // read-side B swizzle

    // Global load assignments
    const int aRow  = tid >> 2;         // 0..63 (+64)
    const int aCol4 = (tid & 3) * 4;    // k offset 0,4,8,12
    const int bKr   = tid >> 5;         // 0..7 (+8)
    const int bN4   = (tid & 31) * 4;   // n offset 0..124
    const int xw    = 8 * (bKr & 3);    // store-side B swizzle (same for bKr+8)

    float c[2][8][4];
    #pragma unroll
    for (int mi = 0; mi < 2; mi++)
        #pragma unroll
        for (int ni = 0; ni < 8; ni++)
            #pragma unroll
            for (int j = 0; j < 4; j++) c[mi][ni][j] = 0.0f;

    const float* Abase = A + (size_t)m0 * K;
    const float* Bbase = B + n0;
    const int nk = K / 16;

    auto ldgA = [&](int kb, float4& a0, float4& a1) {
        a0 = *(const float4*)(Abase + (size_t)aRow        * K + kb * 16 + aCol4);
        a1 = *(const float4*)(Abase + (size_t)(aRow + 64) * K + kb * 16 + aCol4);
    };
    auto ldgB = [&](int kb, float4& b0, float4& b1) {
        b0 = *(const float4*)(Bbase + (size_t)(kb * 16 + bKr)     * N + bN4);
        b1 = *(const float4*)(Bbase + (size_t)(kb * 16 + bKr + 8) * N + bN4);
    };
    auto stsA = [&](int buf, float4 v, int row) {
        float* dh = &Ash[buf * 3072 + row * 24];
        float* dl = &Alo[buf * 3072 + row * 24];
        #pragma unroll
        for (int j = 0; j < 4; j++) {
            int k = aCol4 + j;
            int word = ((k >> 3) << 3) + 2 * (k & 3) + ((k & 7) >> 2);
            float x = (j == 0) ? v.x : (j == 1) ? v.y : (j == 2) ? v.z : v.w;
            float hf = __uint_as_float(f2tf32(x));
            dh[word] = hf;
            dl[word] = __uint_as_float(f2tf32(x - hf));
        }
    };
    auto stsB = [&](int buf, float4 v, int krow) {
        float4 w;
        w.x = __uint_as_float(f2tf32(v.x));
        w.y = __uint_as_float(f2tf32(v.y));
        w.z = __uint_as_float(f2tf32(v.z));
        w.w = __uint_as_float(f2tf32(v.w));
        *(float4*)&Bsm[buf * 2048 + krow * 128 + (bN4 ^ xw)] = w;
    };

    // Prologue
    {
        float4 a0, a1, b0, b1;
        ldgA(0, a0, a1);
        ldgB(0, b0, b1);
        stsA(0, a0, aRow);
        stsA(0, a1, aRow + 64);
        stsB(0, b0, bKr);
        stsB(0, b1, bKr + 8);
    }
    __syncthreads();

    float4 pa0, pa1, pb0, pb1;
    for (int kb = 0; kb < nk; kb++) {
        const int buf = kb & 1;
        const bool more = (kb + 1) < nk;
        if (more) { ldgA(kb + 1, pa0, pa1); ldgB(kb + 1, pb0, pb1); }

        #pragma unroll
        for (int g = 0; g < 2; g++) {
            uint32_t b[8][2];
            #pragma unroll
            for (int ni = 0; ni < 8; ni++) {
                int coln = (wn + ni * 8 + r0) ^ xr;
                b[ni][0] = __float_as_uint(Bsm[buf * 2048 + (g * 8 + c0)     * 128 + coln]);
                b[ni][1] = __float_as_uint(Bsm[buf * 2048 + (g * 8 + c0 + 4) * 128 + coln]);
            }
            #pragma unroll
            for (int mi = 0; mi < 2; mi++) {
                {
                    const uint2 lo = *(const uint2*)&Ash[buf * 3072 + (wr + mi * 16 + r0)     * 24 + g * 8 + 2 * c0];
                    const uint2 hi = *(const uint2*)&Ash[buf * 3072 + (wr + mi * 16 + 8 + r0) * 24 + g * 8 + 2 * c0];
                    uint32_t a[4] = {lo.x, hi.x, lo.y, hi.y};
                    #pragma unroll
                    for (int ni = 0; ni < 8; ni++) mma_tf32(c[mi][ni], a, b[ni]);
                }
                {
                    const uint2 lo = *(const uint2*)&Alo[buf * 3072 + (wr + mi * 16 + r0)     * 24 + g * 8 + 2 * c0];
                    const uint2 hi = *(const uint2*)&Alo[buf * 3072 + (wr + mi * 16 + 8 + r0) * 24 + g * 8 + 2 * c0];
                    uint32_t a[4] = {lo.x, hi.x, lo.y, hi.y};
                    #pragma unroll
                    for (int ni = 0; ni < 8; ni++) mma_tf32(c[mi][ni], a, b[ni]);
                }
            }
        }

        if (more) {
            const int nbuf = buf ^ 1;
            stsA(nbuf, pa0, aRow);
            stsA(nbuf, pa1, aRow + 64);
            stsB(nbuf, pb0, bKr);
            stsB(nbuf, pb1, bKr + 8);
            __syncthreads();
        }
    }

    // Epilogue
    #pragma unroll
    for (int mi = 0; mi < 2; mi++) {
        #pragma unroll
        for (int ni = 0; ni < 8; ni++) {
            int row = m0 + wr + mi * 16 + r0;
            int col = n0 + wn + ni * 8 + 2 * c0;
            float2 v0, v1;
            v0.x = c[mi][ni][0]; v0.y = c[mi][ni][1];
            v1.x = c[mi][ni][2]; v1.y = c[mi][ni][3];
            if (HAS_BIAS) {
                float bx = bias[col], by = bias[col + 1];
                v0.x += bx; v0.y += by;
                v1.x += bx; v1.y += by;
            }
            *(float2*)(C + (size_t)row * N + col)       = v0;
            *(float2*)(C + (size_t)(row + 8) * N + col) = v1;
        }
    }
}

// ---------------------------------------------------------------------------
// Tensor-core flash attention (tf32 mma, causal).
// CTA = 256 threads (8 warps), 256 query rows; warp tile = 32 q-rows.
// K-tile = 64 keys. Q fragments in registers (pre-scaled by 0.125*log2e,
// tf32). K/V in smem [key][dim] stride 68 (bank = 4*r0 + c0, conflict-free).
// S softmax in exp2 domain; P round-trips through per-warp smem [32][36] in
// two 32-key halves, split hi/lo (2xtf32) for accuracy.
// Dynamic smem: K(64*68) | V(64*68) | 8 warps * (Phi[32*36] | Plo[32*36]).
// ---------------------------------------------------------------------------
#define ATT_SMEM ((2 * 64 * 68 + 8 * 2 * 32 * 36) * 4)

__global__ __launch_bounds__(256, 1)
void flash_tc_kernel(const float* __restrict__ qkv, float* __restrict__ out)
{
    extern __shared__ float sm[];
    float* Ksm = sm;                  // [64][68]
    float* Vsm = sm + 64 * 68;        // [64][68]

    const int tid  = threadIdx.x;
    const int lane = tid & 31;
    const int warp = tid >> 5;
    const int r0 = lane >> 2;         // 0..7
    const int c0 = lane & 3;          // 0..3

    float* Phi = sm + 2 * 64 * 68 + warp * (2 * 32 * 36);
    float* Plo = Phi + 32 * 36;

    const int bh = blockIdx.x;        // 0..63
    const int b  = bh >> 4;
    const int h  = bh & 15;
    const int q0 = (7 - (int)blockIdx.y) * 256;   // heavy blocks first
    const int wr = warp * 32;

    const float SC = 0.125f * 1.4426950408889634f;  // (1/sqrt(64)) * log2(e)

    // Q fragments -> registers (once per block)
    uint32_t qa[2][8][4];
    {
        const float* qb = qkv + ((size_t)(b * Tt + q0 + wr)) * NQKV + h * HSd;
        #pragma unroll
        for (int mi = 0; mi < 2; mi++)
            #pragma unroll
            for (int ks = 0; ks < 8; ks++) {
                const float* p0 = qb + (size_t)(mi * 16 + r0)     * NQKV + ks * 8 + c0;
                const float* p1 = qb + (size_t)(mi * 16 + 8 + r0) * NQKV + ks * 8 + c0;
                qa[mi][ks][0] = f2tf32(p0[0] * SC);
                qa[mi][ks][1] = f2tf32(p1[0] * SC);
                qa[mi][ks][2] = f2tf32(p0[4] * SC);
                qa[mi][ks][3] = f2tf32(p1[4] * SC);
            }
    }

    float o[2][8][4];
    #pragma unroll
    for (int mi = 0; mi < 2; mi++)
        #pragma unroll
        for (int ni = 0; ni < 8; ni++)
            #pragma unroll
            for (int j = 0; j < 4; j++) o[mi][ni][j] = 0.0f;
    float mrow[4], lrow[4];
    #pragma unroll
    for (int rs = 0; rs < 4; rs++) { mrow[rs] = -1e30f; lrow[rs] = 0.0f; }

    const float* kgb = qkv + ((size_t)b * Tt) * NQKV + Cc + h * HSd;
    const float* vgb = kgb + Cc;

    const int ntiles = q0 / 64 + 4;
    const int firstMaskTile = q0 / 64;

    for (int kt = 0; kt < ntiles; kt++) {
        __syncthreads();
        // Stage K/V tile (64 keys x 64 dims each), tf32-converted
        #pragma unroll
        for (int i = 0; i < 4; i++) {
            int idx = i * 256 + tid;          // 0..1023 float4 slots
            int row = idx >> 4;
            int cc4 = (idx & 15) << 2;
            float4 kv = *(const float4*)(kgb + (size_t)(kt * 64 + row) * NQKV + cc4);
            float4 vv = *(const float4*)(vgb + (size_t)(kt * 64 + row) * NQKV + cc4);
            float4 kc, vc;
            kc.x = __uint_as_float(f2tf32(kv.x)); kc.y = __uint_as_float(f2tf32(kv.y));
            kc.z = __uint_as_float(f2tf32(kv.z)); kc.w = __uint_as_float(f2tf32(kv.w));
            vc.x = __uint_as_float(f2tf32(vv.x)); vc.y = __uint_as_float(f2tf32(vv.y));
            vc.z = __uint_as_float(f2tf32(vv.z)); vc.w = __uint_as_float(f2tf32(vv.w));
            *(float4*)&Ksm[row * 68 + cc4] = kc;
            *(float4*)&Vsm[row * 68 + cc4] = vc;
        }
        __syncthreads();

        // S = Q K^T
        float s[2][8][4];
        #pragma unroll
        for (int mi = 0; mi < 2; mi++)
            #pragma unroll
            for (int ni = 0; ni < 8; ni++)
                #pragma unroll
                for (int j = 0; j < 4; j++) s[mi][ni][j] = 0.0f;

        #pragma unroll
        for (int ks = 0; ks < 8; ks++) {
            #pragma unroll
            for (int ni = 0; ni < 8; ni++) {
                uint32_t bb[2];
                bb[0] = __float_as_uint(Ksm[(ni * 8 + r0) * 68 + ks * 8 + c0]);
                bb[1] = __float_as_uint(Ksm[(ni * 8 + r0) * 68 + ks * 8 + c0 + 4]);
                mma_tf32(s[0][ni], qa[0][ks], bb);
                mma_tf32(s[1][ni], qa[1][ks], bb);
            }
        }

        // Causal mask (only needed on the 4 diagonal tiles)
        if (kt >= firstMaskTile) {
            #pragma unroll
            for (int mi = 0; mi < 2; mi++) {
                int row = q0 + wr + mi * 16 + r0;
                #pragma unroll
                for (int ni = 0; ni < 8; ni++) {
                    int key = kt * 64 + ni * 8 + 2 * c0;
                    if (key     > row)     s[mi][ni][0] = -1e30f;
                    if (key + 1 > row)     s[mi][ni][1] = -1e30f;
                    if (key     > row + 8) s[mi][ni][2] = -1e30f;
                    if (key + 1 > row + 8) s[mi][ni][3] = -1e30f;
                }
            }
        }

        // Online softmax (exp2 domain); s becomes p
        #pragma unroll
        for (int mi = 0; mi < 2; mi++) {
            #pragma unroll
            for (int h2 = 0; h2 < 2; h2++) {
                const int rs = mi * 2 + h2;
                float mx = -1e30f;
                #pragma unroll
                for (int ni = 0; ni < 8; ni++)
                    mx = fmaxf(mx, fmaxf(s[mi][ni][2 * h2], s[mi][ni][2 * h2 + 1]));
                mx = fmaxf(mx, __shfl_xor_sync(0xffffffffu, mx, 1));
                mx = fmaxf(mx, __shfl_xor_sync(0xffffffffu, mx, 2));
                float mnew = fmaxf(mrow[rs], mx);
                float corr = exp2fast(mrow[rs] - mnew);
                mrow[rs] = mnew;
                float psum = 0.0f;
                #pragma unroll
                for (int ni = 0; ni < 8; ni++) {
                    float p0 = exp2fast(s[mi][ni][2 * h2]     - mnew);
                    float p1 = exp2fast(s[mi][ni][2 * h2 + 1] - mnew);
                    s[mi][ni][2 * h2]     = p0;
                    s[mi][ni][2 * h2 + 1] = p1;
                    psum += p0 + p1;
                }
                lrow[rs] = lrow[rs] * corr + psum;
                #pragma unroll
                for (int ni = 0; ni < 8; ni++) {
                    o[mi][ni][2 * h2]     *= corr;
                    o[mi][ni][2 * h2 + 1] *= corr;
                }
            }
        }

        // O += P V, in two 32-key halves, P split hi/lo
        #pragma unroll
        for (int hk = 0; hk < 2; hk++) {
            #pragma unroll
            for (int mi = 0; mi < 2; mi++) {
                #pragma unroll
                for (int h2 = 0; h2 < 2; h2++) {
                    int rloc = mi * 16 + h2 * 8 + r0;
                    #pragma unroll
                    for (int j = 0; j < 4; j++) {
                        float p0f = s[mi][hk * 4 + j][2 * h2];
                        float p1f = s[mi][hk * 4 + j][2 * h2 + 1];
                        float h0 = __uint_as_float(f2tf32(p0f));
                        float h1 = __uint_as_float(f2tf32(p1f));
                        float l0 = __uint_as_float(f2tf32(p0f - h0));
                        float l1 = __uint_as_float(f2tf32(p1f - h1));
                        *(float2*)&Phi[rloc * 36 + j * 8 + 2 * c0] = make_float2(h0, h1);
                        *(float2*)&Plo[rloc * 36 + j * 8 + 2 * c0] = make_float2(l0, l1);
                    }
                }
            }
            __syncwarp();
            #pragma unroll
            for (int ks = 0; ks < 4; ks++) {
                uint32_t ah[2][4], al[2][4];
                #pragma unroll
                for (int mi = 0; mi < 2; mi++) {
                    int ra = mi * 16 + r0;
                    ah[mi][0] = __float_as_uint(Phi[ra * 36 + ks * 8 + c0]);
                    ah[mi][1] = __float_as_uint(Phi[(ra + 8) * 36 + ks * 8 + c0]);
                    ah[mi][2] = __float_as_uint(Phi[ra * 36 + ks * 8 + c0 + 4]);
                    ah[mi][3] = __float_as_uint(Phi[(ra + 8) * 36 + ks * 8 + c0 + 4]);
                    al[mi][0] = __float_as_uint(Plo[ra * 36 + ks * 8 + c0]);
                    al[mi][1] = __float_as_uint(Plo[(ra + 8) * 36 + ks * 8 + c0]);
                    al[mi][2] = __float_as_uint(Plo[ra * 36 + ks * 8 + c0 + 4]);
                    al[mi][3] = __float_as_uint(Plo[(ra + 8) * 36 + ks * 8 + c0 + 4]);
                }
                #pragma unroll
                for (int ni = 0; ni < 8; ni++) {
                    uint32_t bb[2];
                    int vrow = hk * 32 + ks * 8 + c0;
                    bb[0] = __float_as_uint(Vsm[vrow * 68 + ni * 8 + r0]);
                    bb[1] = __float_as_uint(Vsm[(vrow + 4) * 68 + ni * 8 + r0]);
                    mma_tf32(o[0][ni], ah[0], bb);
                    mma_tf32(o[1][ni], ah[1], bb);
                    mma_tf32(o[0][ni], al[0], bb);
                    mma_tf32(o[1][ni], al[1], bb);
                }
            }
            __syncwarp();
        }
    }

    // Final normalize + write
    float linv[4];
    #pragma unroll
    for (int rs = 0; rs < 4; rs++) {
        float l = lrow[rs];
        l += __shfl_xor_sync(0xffffffffu, l, 1);
        l += __shfl_xor_sync(0xffffffffu, l, 2);
        linv[rs] = 1.0f / l;
    }
    float* ob = out + ((size_t)(b * Tt + q0 + wr)) * Cc + h * HSd;
    #pragma unroll
    for (int mi = 0; mi < 2; mi++) {
        #pragma unroll
        for (int h2 = 0; h2 < 2; h2++) {
            int rloc = mi * 16 + h2 * 8 + r0;
            float inv = linv[mi * 2 + h2];
            #pragma unroll
            for (int ni = 0; ni < 8; ni++) {
                float2 v;
                v.x = o[mi][ni][2 * h2]     * inv;
                v.y = o[mi][ni][2 * h2 + 1] * inv;
                *(float2*)(ob + (size_t)rloc * Cc + ni * 8 + 2 * c0) = v;
            }
        }
    }
}

// ---------------------------------------------------------------------------
extern "C" void kernel_launch(void* const* d_in, const int* in_sizes, int n_in,
                              void* d_out, int out_size)
{
    const float* x     = (const float*)d_in[0];   // [B,T,C]
    const float* Wqkv  = (const float*)d_in[1];   // [C,3C]
    const float* Wproj = (const float*)d_in[2];   // [C,C]
    const float* bproj = (const float*)d_in[3];   // [C]
    float* out = (float*)d_out;                   // [B,T,C]

    float *qkv, *attn;
    cudaGetSymbolAddress((void**)&qkv,  g_qkv);
    cudaGetSymbolAddress((void**)&attn, g_attn);

    const int GEMM_SMEM = 16384 * 4;   // 64 KB
    cudaFuncSetAttribute(tgemm_kernel<false>,
                         cudaFuncAttributeMaxDynamicSharedMemorySize, GEMM_SMEM);
    cudaFuncSetAttribute(tgemm_kernel<true>,
                         cudaFuncAttributeMaxDynamicSharedMemorySize, GEMM_SMEM);
    cudaFuncSetAttribute(flash_tc_kernel,
                         cudaFuncAttributeMaxDynamicSharedMemorySize, ATT_SMEM);

    dim3 blk(256);
    // 1) QKV projection: [8192,1024] @ [1024,3072]
    tgemm_kernel<false><<<dim3(NQKV / 128, Mm / 128), blk, GEMM_SMEM>>>(
        x, Wqkv, nullptr, qkv, Mm, NQKV, Cc);
    // 2) Causal flash attention (tensor cores) -> [B,T,C]
    flash_tc_kernel<<<dim3(Bb * Hh, Tt / 256), blk, ATT_SMEM>>>(qkv, attn);
    // 3) Output projection + bias: [8192,1024] @ [1024,1024]
    tgemm_kernel<true><<<dim3(Cc / 128, Mm / 128), blk, GEMM_SMEM>>>(
        attn, Wproj, bproj, out, Mm, Cc, Cc);
}

// round 6
// speedup vs baseline: 3.2333x; 1.3448x over previous
#include <cuda_runtime.h>
#include <math.h>
#include <stdint.h>

// Problem constants
#define Bb   4
#define Tt   2048
#define Cc   1024
#define Hh   16
#define HSd  64
#define Mm   (Bb * Tt)      // 8192
#define NQKV (3 * Cc)       // 3072

// Scratch (static device globals: allocation rules forbid cudaMalloc)
__device__ float g_qkv[(size_t)Mm * NQKV];    // [B*T, 3C] : q|k|v
__device__ float g_attn[(size_t)Mm * Cc];     // [B*T, C]  : attention out

// ---------------------------------------------------------------------------
// tf32 helpers
// ---------------------------------------------------------------------------
static __device__ __forceinline__ uint32_t f2tf32(float x) {
    uint32_t y;
    asm("cvt.rna.tf32.f32 %0, %1;" : "=r"(y) : "f"(x));
    return y;
}

static __device__ __forceinline__ float exp2fast(float x) {
    float y;
    asm("ex2.approx.f32 %0, %1;" : "=f"(y) : "f"(x));
    return y;
}

static __device__ __forceinline__ void mma_tf32(float c[4], const uint32_t a[4],
                                                const uint32_t b[2]) {
    asm volatile(
        "mma.sync.aligned.m16n8k8.row.col.f32.tf32.tf32.f32 "
        "{%0,%1,%2,%3}, {%4,%5,%6,%7}, {%8,%9}, {%0,%1,%2,%3};\n"
        : "+f"(c[0]), "+f"(c[1]), "+f"(c[2]), "+f"(c[3])
        : "r"(a[0]), "r"(a[1]), "r"(a[2]), "r"(a[3]), "r"(b[0]), "r"(b[1]));
}

// ---------------------------------------------------------------------------
// tf32 tensor-core GEMM: C = tf32(A) @ tf32(B) (+ bias).
// 128x128 tile, BK=32, 256 threads (8 warps, 4x2), warp tile 32x64.
// Double-buffered smem.
// A layout: [row][40] with k-pair permutation
//   word(r,k) = (k>>3)*8 + 2*(k&3) + ((k&7)>>2)
// -> conflict-free LDS.64 per A fragment half (stride 40: r0*8 mod 32 cycles
//    {0,8,16,24} within each 16-lane phase).
// B layout: [k][128] with XOR swizzle col ^= 8*(k&3) -> conflict-free LDS.32.
// Dynamic smem: As(2*128*40) + Bs(2*32*128) floats = 72 KB.
// ---------------------------------------------------------------------------
template <bool HAS_BIAS>
__global__ __launch_bounds__(256, 2)
void tgemm_kernel(const float* __restrict__ A, const float* __restrict__ B,
                  const float* __restrict__ bias, float* __restrict__ C,
                  int M, int N, int K)
{
    extern __shared__ float smg[];
    float* Ash = smg;               // [2][128*40]
    float* Bsm = smg + 10240;       // [2][32*128]

    const int tid  = threadIdx.x;
    const int lane = tid & 31;
    const int warp = tid >> 5;
    const int m0 = blockIdx.y * 128;
    const int n0 = blockIdx.x * 128;
    const int wr = (warp & 3) * 32;   // warp m offset
    const int wn = (warp >> 2) * 64;  // warp n offset
    const int r0 = lane >> 2;         // 0..7
    const int c0 = lane & 3;          // 0..3
    const int xr = 8 * c0;            // read-side B swizzle

    // Global load assignments (BK=32)
    const int aRow  = tid >> 3;         // 0..31 (+32,+64,+96)
    const int aCol4 = (tid & 7) * 4;    // k offset 0..28
    const int bKr   = tid >> 5;         // 0..7 (+8,+16,+24)
    const int bN4   = (tid & 31) * 4;   // n offset 0..124
    const int xw    = 8 * (bKr & 3);    // store-side B swizzle

    float c[2][8][4];
    #pragma unroll
    for (int mi = 0; mi < 2; mi++)
        #pragma unroll
        for (int ni = 0; ni < 8; ni++)
            #pragma unroll
            for (int j = 0; j < 4; j++) c[mi][ni][j] = 0.0f;

    const float* Abase = A + (size_t)m0 * K;
    const float* Bbase = B + n0;
    const int nk = K / 32;

    auto ldgA = [&](int kb, float4 a[4]) {
        #pragma unroll
        for (int i = 0; i < 4; i++)
            a[i] = *(const float4*)(Abase + (size_t)(aRow + i * 32) * K + kb * 32 + aCol4);
    };
    auto ldgB = [&](int kb, float4 b[4]) {
        #pragma unroll
        for (int i = 0; i < 4; i++)
            b[i] = *(const float4*)(Bbase + (size_t)(kb * 32 + bKr + i * 8) * N + bN4);
    };
    auto stsA = [&](int buf, const float4 a[4]) {
        #pragma unroll
        for (int i = 0; i < 4; i++) {
            float* dst = &Ash[buf * 5120 + (aRow + i * 32) * 40];
            #pragma unroll
            for (int j = 0; j < 4; j++) {
                int k = aCol4 + j;
                int word = ((k >> 3) << 3) + 2 * (k & 3) + ((k & 7) >> 2);
                float x = (j == 0) ? a[i].x : (j == 1) ? a[i].y : (j == 2) ? a[i].z : a[i].w;
                dst[word] = __uint_as_float(f2tf32(x));
            }
        }
    };
    auto stsB = [&](int buf, const float4 b[4]) {
        #pragma unroll
        for (int i = 0; i < 4; i++) {
            float4 w;
            w.x = __uint_as_float(f2tf32(b[i].x));
            w.y = __uint_as_float(f2tf32(b[i].y));
            w.z = __uint_as_float(f2tf32(b[i].z));
            w.w = __uint_as_float(f2tf32(b[i].w));
            *(float4*)&Bsm[buf * 4096 + (bKr + i * 8) * 128 + (bN4 ^ xw)] = w;
        }
    };

    // Prologue
    {
        float4 a[4], b[4];
        ldgA(0, a);
        ldgB(0, b);
        stsA(0, a);
        stsB(0, b);
    }
    __syncthreads();

    float4 pa[4], pb[4];
    for (int kb = 0; kb < nk; kb++) {
        const int buf = kb & 1;
        const bool more = (kb + 1) < nk;
        if (more) { ldgA(kb + 1, pa); ldgB(kb + 1, pb); }

        #pragma unroll
        for (int g = 0; g < 4; g++) {
            uint32_t b[8][2];
            #pragma unroll
            for (int ni = 0; ni < 8; ni++) {
                int coln = (wn + ni * 8 + r0) ^ xr;
                b[ni][0] = __float_as_uint(Bsm[buf * 4096 + (g * 8 + c0)     * 128 + coln]);
                b[ni][1] = __float_as_uint(Bsm[buf * 4096 + (g * 8 + c0 + 4) * 128 + coln]);
            }
            #pragma unroll
            for (int mi = 0; mi < 2; mi++) {
                const uint2 lo = *(const uint2*)&Ash[buf * 5120 + (wr + mi * 16 + r0)     * 40 + g * 8 + 2 * c0];
                const uint2 hi = *(const uint2*)&Ash[buf * 5120 + (wr + mi * 16 + 8 + r0) * 40 + g * 8 + 2 * c0];
                uint32_t a[4] = {lo.x, hi.x, lo.y, hi.y};
                #pragma unroll
                for (int ni = 0; ni < 8; ni++) mma_tf32(c[mi][ni], a, b[ni]);
            }
        }

        if (more) {
            const int nbuf = buf ^ 1;
            stsA(nbuf, pa);
            stsB(nbuf, pb);
            __syncthreads();
        }
    }

    // Epilogue
    #pragma unroll
    for (int mi = 0; mi < 2; mi++) {
        #pragma unroll
        for (int ni = 0; ni < 8; ni++) {
            int row = m0 + wr + mi * 16 + r0;
            int col = n0 + wn + ni * 8 + 2 * c0;
            float2 v0, v1;
            v0.x = c[mi][ni][0]; v0.y = c[mi][ni][1];
            v1.x = c[mi][ni][2]; v1.y = c[mi][ni][3];
            if (HAS_BIAS) {
                float bx = bias[col], by = bias[col + 1];
                v0.x += bx; v0.y += by;
                v1.x += bx; v1.y += by;
            }
            *(float2*)(C + (size_t)row * N + col)       = v0;
            *(float2*)(C + (size_t)(row + 8) * N + col) = v1;
        }
    }
}

// ---------------------------------------------------------------------------
// Tensor-core flash attention (tf32 mma, causal).
// CTA = 256 threads (8 warps), 256 query rows; warp tile = 32 q-rows.
// K-tile = 64 keys. Q fragments in registers (pre-scaled by 0.125*log2e,
// tf32). K/V in smem [key][dim] stride 68 (conflict-free scalar reads).
// S softmax in exp2 domain; P round-trips through per-warp smem [32][36]
// (tf32) in two 32-key halves.
// Dynamic smem: K(64*68) | V(64*68) | 8 warps * P[32*36]  = 70 KB.
// ---------------------------------------------------------------------------
#define ATT_SMEM ((2 * 64 * 68 + 8 * 32 * 36) * 4)

__global__ __launch_bounds__(256, 1)
void flash_tc_kernel(const float* __restrict__ qkv, float* __restrict__ out)
{
    extern __shared__ float sm[];
    float* Ksm = sm;                  // [64][68]
    float* Vsm = sm + 64 * 68;        // [64][68]

    const int tid  = threadIdx.x;
    const int lane = tid & 31;
    const int warp = tid >> 5;
    const int r0 = lane >> 2;         // 0..7
    const int c0 = lane & 3;          // 0..3

    float* Phi = sm + 2 * 64 * 68 + warp * (32 * 36);

    const int bh = blockIdx.x;        // 0..63
    const int b  = bh >> 4;
    const int h  = bh & 15;
    const int q0 = (7 - (int)blockIdx.y) * 256;   // heavy blocks first
    const int wr = warp * 32;

    const float SC = 0.125f * 1.4426950408889634f;  // (1/sqrt(64)) * log2(e)

    // Q fragments -> registers (once per block)
    uint32_t qa[2][8][4];
    {
        const float* qb = qkv + ((size_t)(b * Tt + q0 + wr)) * NQKV + h * HSd;
        #pragma unroll
        for (int mi = 0; mi < 2; mi++)
            #pragma unroll
            for (int ks = 0; ks < 8; ks++) {
                const float* p0 = qb + (size_t)(mi * 16 + r0)     * NQKV + ks * 8 + c0;
                const float* p1 = qb + (size_t)(mi * 16 + 8 + r0) * NQKV + ks * 8 + c0;
                qa[mi][ks][0] = f2tf32(p0[0] * SC);
                qa[mi][ks][1] = f2tf32(p1[0] * SC);
                qa[mi][ks][2] = f2tf32(p0[4] * SC);
                qa[mi][ks][3] = f2tf32(p1[4] * SC);
            }
    }

    float o[2][8][4];
    #pragma unroll
    for (int mi = 0; mi < 2; mi++)
        #pragma unroll
        for (int ni = 0; ni < 8; ni++)
            #pragma unroll
            for (int j = 0; j < 4; j++) o[mi][ni][j] = 0.0f;
    float mrow[4], lrow[4];
    #pragma unroll
    for (int rs = 0; rs < 4; rs++) { mrow[rs] = -1e30f; lrow[rs] = 0.0f; }

    const float* kgb = qkv + ((size_t)b * Tt) * NQKV + Cc + h * HSd;
    const float* vgb = kgb + Cc;

    const int ntiles = q0 / 64 + 4;
    const int firstMaskTile = q0 / 64;

    for (int kt = 0; kt < ntiles; kt++) {
        __syncthreads();
        // Stage K/V tile (64 keys x 64 dims each), tf32-converted
        #pragma unroll
        for (int i = 0; i < 4; i++) {
            int idx = i * 256 + tid;          // 0..1023 float4 slots
            int row = idx >> 4;
            int cc4 = (idx & 15) << 2;
            float4 kv = *(const float4*)(kgb + (size_t)(kt * 64 + row) * NQKV + cc4);
            float4 vv = *(const float4*)(vgb + (size_t)(kt * 64 + row) * NQKV + cc4);
            float4 kc, vc;
            kc.x = __uint_as_float(f2tf32(kv.x)); kc.y = __uint_as_float(f2tf32(kv.y));
            kc.z = __uint_as_float(f2tf32(kv.z)); kc.w = __uint_as_float(f2tf32(kv.w));
            vc.x = __uint_as_float(f2tf32(vv.x)); vc.y = __uint_as_float(f2tf32(vv.y));
            vc.z = __uint_as_float(f2tf32(vv.z)); vc.w = __uint_as_float(f2tf32(vv.w));
            *(float4*)&Ksm[row * 68 + cc4] = kc;
            *(float4*)&Vsm[row * 68 + cc4] = vc;
        }
        __syncthreads();

        // S = Q K^T
        float s[2][8][4];
        #pragma unroll
        for (int mi = 0; mi < 2; mi++)
            #pragma unroll
            for (int ni = 0; ni < 8; ni++)
                #pragma unroll
                for (int j = 0; j < 4; j++) s[mi][ni][j] = 0.0f;

        #pragma unroll
        for (int ks = 0; ks < 8; ks++) {
            #pragma unroll
            for (int ni = 0; ni < 8; ni++) {
                uint32_t bb[2];
                bb[0] = __float_as_uint(Ksm[(ni * 8 + r0) * 68 + ks * 8 + c0]);
                bb[1] = __float_as_uint(Ksm[(ni * 8 + r0) * 68 + ks * 8 + c0 + 4]);
                mma_tf32(s[0][ni], qa[0][ks], bb);
                mma_tf32(s[1][ni], qa[1][ks], bb);
            }
        }

        // Causal mask (only on the 4 diagonal tiles)
        if (kt >= firstMaskTile) {
            #pragma unroll
            for (int mi = 0; mi < 2; mi++) {
                int row = q0 + wr + mi * 16 + r0;
                #pragma unroll
                for (int ni = 0; ni < 8; ni++) {
                    int key = kt * 64 + ni * 8 + 2 * c0;
                    if (key     > row)     s[mi][ni][0] = -1e30f;
                    if (key + 1 > row)     s[mi][ni][1] = -1e30f;
                    if (key     > row + 8) s[mi][ni][2] = -1e30f;
                    if (key + 1 > row + 8) s[mi][ni][3] = -1e30f;
                }
            }
        }

        // Online softmax (exp2 domain); s becomes p
        #pragma unroll
        for (int mi = 0; mi < 2; mi++) {
            #pragma unroll
            for (int h2 = 0; h2 < 2; h2++) {
                const int rs = mi * 2 + h2;
                float mx = -1e30f;
                #pragma unroll
                for (int ni = 0; ni < 8; ni++)
                    mx = fmaxf(mx, fmaxf(s[mi][ni][2 * h2], s[mi][ni][2 * h2 + 1]));
                mx = fmaxf(mx, __shfl_xor_sync(0xffffffffu, mx, 1));
                mx = fmaxf(mx, __shfl_xor_sync(0xffffffffu, mx, 2));
                float mnew = fmaxf(mrow[rs], mx);
                float corr = exp2fast(mrow[rs] - mnew);
                mrow[rs] = mnew;
                float psum = 0.0f;
                #pragma unroll
                for (int ni = 0; ni < 8; ni++) {
                    float p0 = exp2fast(s[mi][ni][2 * h2]     - mnew);
                    float p1 = exp2fast(s[mi][ni][2 * h2 + 1] - mnew);
                    s[mi][ni][2 * h2]     = p0;
                    s[mi][ni][2 * h2 + 1] = p1;
                    psum += p0 + p1;
                }
                lrow[rs] = lrow[rs] * corr + psum;
                #pragma unroll
                for (int ni = 0; ni < 8; ni++) {
                    o[mi][ni][2 * h2]     *= corr;
                    o[mi][ni][2 * h2 + 1] *= corr;
                }
            }
        }

        // O += P V, in two 32-key halves (P tf32 via per-warp smem)
        #pragma unroll
        for (int hk = 0; hk < 2; hk++) {
            #pragma unroll
            for (int mi = 0; mi < 2; mi++) {
                #pragma unroll
                for (int h2 = 0; h2 < 2; h2++) {
                    int rloc = mi * 16 + h2 * 8 + r0;
                    #pragma unroll
                    for (int j = 0; j < 4; j++) {
                        float h0 = __uint_as_float(f2tf32(s[mi][hk * 4 + j][2 * h2]));
                        float h1 = __uint_as_float(f2tf32(s[mi][hk * 4 + j][2 * h2 + 1]));
                        *(float2*)&Phi[rloc * 36 + j * 8 + 2 * c0] = make_float2(h0, h1);
                    }
                }
            }
            __syncwarp();
            #pragma unroll
            for (int ks = 0; ks < 4; ks++) {
                uint32_t ah[2][4];
                #pragma unroll
                for (int mi = 0; mi < 2; mi++) {
                    int ra = mi * 16 + r0;
                    ah[mi][0] = __float_as_uint(Phi[ra * 36 + ks * 8 + c0]);
                    ah[mi][1] = __float_as_uint(Phi[(ra + 8) * 36 + ks * 8 + c0]);
                    ah[mi][2] = __float_as_uint(Phi[ra * 36 + ks * 8 + c0 + 4]);
                    ah[mi][3] = __float_as_uint(Phi[(ra + 8) * 36 + ks * 8 + c0 + 4]);
                }
                #pragma unroll
                for (int ni = 0; ni < 8; ni++) {
                    uint32_t bb[2];
                    int vrow = hk * 32 + ks * 8 + c0;
                    bb[0] = __float_as_uint(Vsm[vrow * 68 + ni * 8 + r0]);
                    bb[1] = __float_as_uint(Vsm[(vrow + 4) * 68 + ni * 8 + r0]);
                    mma_tf32(o[0][ni], ah[0], bb);
                    mma_tf32(o[1][ni], ah[1], bb);
                }
            }
            __syncwarp();
        }
    }

    // Final normalize + write
    float linv[4];
    #pragma unroll
    for (int rs = 0; rs < 4; rs++) {
        float l = lrow[rs];
        l += __shfl_xor_sync(0xffffffffu, l, 1);
        l += __shfl_xor_sync(0xffffffffu, l, 2);
        linv[rs] = 1.0f / l;
    }
    float* ob = out + ((size_t)(b * Tt + q0 + wr)) * Cc + h * HSd;
    #pragma unroll
    for (int mi = 0; mi < 2; mi++) {
        #pragma unroll
        for (int h2 = 0; h2 < 2; h2++) {
            int rloc = mi * 16 + h2 * 8 + r0;
            float inv = linv[mi * 2 + h2];
            #pragma unroll
            for (int ni = 0; ni < 8; ni++) {
                float2 v;
                v.x = o[mi][ni][2 * h2]     * inv;
                v.y = o[mi][ni][2 * h2 + 1] * inv;
                *(float2*)(ob + (size_t)rloc * Cc + ni * 8 + 2 * c0) = v;
            }
        }
    }
}

// ---------------------------------------------------------------------------
extern "C" void kernel_launch(void* const* d_in, const int* in_sizes, int n_in,
                              void* d_out, int out_size)
{
    const float* x     = (const float*)d_in[0];   // [B,T,C]
    const float* Wqkv  = (const float*)d_in[1];   // [C,3C]
    const float* Wproj = (const float*)d_in[2];   // [C,C]
    const float* bproj = (const float*)d_in[3];   // [C]
    float* out = (float*)d_out;                   // [B,T,C]

    float *qkv, *attn;
    cudaGetSymbolAddress((void**)&qkv,  g_qkv);
    cudaGetSymbolAddress((void**)&attn, g_attn);

    const int GEMM_SMEM = 18432 * 4;   // 72 KB
    cudaFuncSetAttribute(tgemm_kernel<false>,
                         cudaFuncAttributeMaxDynamicSharedMemorySize, GEMM_SMEM);
    cudaFuncSetAttribute(tgemm_kernel<true>,
                         cudaFuncAttributeMaxDynamicSharedMemorySize, GEMM_SMEM);
    cudaFuncSetAttribute(flash_tc_kernel,
                         cudaFuncAttributeMaxDynamicSharedMemorySize, ATT_SMEM);

    dim3 blk(256);
    // 1) QKV projection: [8192,1024] @ [1024,3072]
    tgemm_kernel<false><<<dim3(NQKV / 128, Mm / 128), blk, GEMM_SMEM>>>(
        x, Wqkv, nullptr, qkv, Mm, NQKV, Cc);
    // 2) Causal flash attention (tensor cores) -> [B,T,C]
    flash_tc_kernel<<<dim3(Bb * Hh, Tt / 256), blk, ATT_SMEM>>>(qkv, attn);
    // 3) Output projection + bias: [8192,1024] @ [1024,1024]
    tgemm_kernel<true><<<dim3(Cc / 128, Mm / 128), blk, GEMM_SMEM>>>(
        attn, Wproj, bproj, out, Mm, Cc, Cc);
}

// round 8
// speedup vs baseline: 3.3555x; 1.0378x over previous
#include <cuda_runtime.h>
#include <math.h>
#include <stdint.h>

// Problem constants
#define Bb   4
#define Tt   2048
#define Cc   1024
#define Hh   16
#define HSd  64
#define Mm   (Bb * Tt)      // 8192
#define NQKV (3 * Cc)       // 3072

// Scratch (static device globals: allocation rules forbid cudaMalloc)
__device__ float g_qkv[(size_t)Mm * NQKV];     // [B*T, 3C] tf32 (q pre-scaled by SC_Q)
__device__ float g_attn[(size_t)Mm * Cc];      // [B*T, C] tf32 attention out
__device__ float g_xc[(size_t)Mm * Cc];        // x, tf32
__device__ float g_wqkv_c[(size_t)Cc * NQKV];  // W_qkv, tf32, [K][N]
__device__ float g_wproj_c[(size_t)Cc * Cc];   // W_proj, tf32, [K][N]

// ---------------------------------------------------------------------------
// helpers
// ---------------------------------------------------------------------------
static __device__ __forceinline__ uint32_t f2tf32(float x) {
    uint32_t y;
    asm("cvt.rna.tf32.f32 %0, %1;" : "=r"(y) : "f"(x));
    return y;
}

static __device__ __forceinline__ float exp2fast(float x) {
    float y;
    asm("ex2.approx.f32 %0, %1;" : "=f"(y) : "f"(x));
    return y;
}

static __device__ __forceinline__ void mma_tf32(float c[4], const uint32_t a[4],
                                                const uint32_t b[2]) {
    asm volatile(
        "mma.sync.aligned.m16n8k8.row.col.f32.tf32.tf32.f32 "
        "{%0,%1,%2,%3}, {%4,%5,%6,%7}, {%8,%9}, {%0,%1,%2,%3};\n"
        : "+f"(c[0]), "+f"(c[1]), "+f"(c[2]), "+f"(c[3])
        : "r"(a[0]), "r"(a[1]), "r"(a[2]), "r"(a[3]), "r"(b[0]), "r"(b[1]));
}

#define SC_Q (0.125f * 1.4426950408889634f)   // (1/sqrt(64)) * log2(e)

// ---------------------------------------------------------------------------
// Prepass: elementwise tf32-round (vectorized)
// ---------------------------------------------------------------------------
__global__ void cvt_kernel(const float* __restrict__ in, float* __restrict__ out,
                           int n4)
{
    int i = blockIdx.x * blockDim.x + threadIdx.x;
    if (i < n4) {
        float4 v = ((const float4*)in)[i];
        v.x = __uint_as_float(f2tf32(v.x));
        v.y = __uint_as_float(f2tf32(v.y));
        v.z = __uint_as_float(f2tf32(v.z));
        v.w = __uint_as_float(f2tf32(v.w));
        ((float4*)out)[i] = v;
    }
}

// ---------------------------------------------------------------------------
// tf32 tensor-core GEMM: C = A @ B (+ epilogue). Inputs ALREADY tf32-rounded.
// 128x128 tile, BK=32, 256 threads (8 warps, 4x2), warp tile 32x64.
// Double-buffered smem; raw-copy staging (no cvts in mainloop).
// A layout: [row][40], k-pair permutation word(k) = (k>>3)*8+2*(k&3)+((k&7)>>2)
//   -> conflict-free LDS.64 fragments.
// B layout: [k][128], XOR swizzle col ^= 8*(k&3) -> conflict-free LDS.32.
// MODE 0 (QKV): cols < Cc (q) scaled by SC_Q; all outputs tf32-rounded.
// MODE 1 (proj): + bias, fp32 out.
// Dyn smem: As(2*128*40) + Bs(2*32*128) floats = 72 KB.
// ---------------------------------------------------------------------------
template <int MODE>
__global__ __launch_bounds__(256, 2)
void tgemm_kernel(const float* __restrict__ A, const float* __restrict__ B,
                  const float* __restrict__ bias, float* __restrict__ C,
                  int M, int N, int K)
{
    extern __shared__ float smg[];
    float* Ash = smg;               // [2][128*40]
    float* Bsm = smg + 10240;       // [2][32*128]

    const int tid  = threadIdx.x;
    const int lane = tid & 31;
    const int warp = tid >> 5;
    const int m0 = blockIdx.y * 128;
    const int n0 = blockIdx.x * 128;
    const int wr = (warp & 3) * 32;   // warp m offset
    const int wn = (warp >> 2) * 64;  // warp n offset
    const int r0 = lane >> 2;         // 0..7
    const int c0 = lane & 3;          // 0..3
    const int xr = 8 * c0;            // read-side B swizzle

    // Global load assignments (BK=32)
    const int aRow  = tid >> 3;         // 0..31 (+32,+64,+96)
    const int aCol4 = (tid & 7) * 4;    // k offset 0..28
    const int bKr   = tid >> 5;         // 0..7 (+8,+16,+24)
    const int bN4   = (tid & 31) * 4;   // n offset 0..124
    const int xw    = 8 * (bKr & 3);    // store-side B swizzle

    float c[2][8][4];
    #pragma unroll
    for (int mi = 0; mi < 2; mi++)
        #pragma unroll
        for (int ni = 0; ni < 8; ni++)
            #pragma unroll
            for (int j = 0; j < 4; j++) c[mi][ni][j] = 0.0f;

    const float* Abase = A + (size_t)m0 * K;
    const float* Bbase = B + n0;
    const int nk = K / 32;

    auto ldgA = [&](int kb, float4 a[4]) {
        #pragma unroll
        for (int i = 0; i < 4; i++)
            a[i] = *(const float4*)(Abase + (size_t)(aRow + i * 32) * K + kb * 32 + aCol4);
    };
    auto ldgB = [&](int kb, float4 b[4]) {
        #pragma unroll
        for (int i = 0; i < 4; i++)
            b[i] = *(const float4*)(Bbase + (size_t)(kb * 32 + bKr + i * 8) * N + bN4);
    };
    auto stsA = [&](int buf, const float4 a[4]) {
        #pragma unroll
        for (int i = 0; i < 4; i++) {
            float* dst = &Ash[buf * 5120 + (aRow + i * 32) * 40];
            #pragma unroll
            for (int j = 0; j < 4; j++) {
                int k = aCol4 + j;
                int word = ((k >> 3) << 3) + 2 * (k & 3) + ((k & 7) >> 2);
                float x = (j == 0) ? a[i].x : (j == 1) ? a[i].y : (j == 2) ? a[i].z : a[i].w;
                dst[word] = x;    // raw copy (already tf32)
            }
        }
    };
    auto stsB = [&](int buf, const float4 b[4]) {
        #pragma unroll
        for (int i = 0; i < 4; i++)
            *(float4*)&Bsm[buf * 4096 + (bKr + i * 8) * 128 + (bN4 ^ xw)] = b[i];
    };

    // Prologue
    {
        float4 a[4], b[4];
        ldgA(0, a);
        ldgB(0, b);
        stsA(0, a);
        stsB(0, b);
    }
    __syncthreads();

    float4 pa[4], pb[4];
    for (int kb = 0; kb < nk; kb++) {
        const int buf = kb & 1;
        const bool more = (kb + 1) < nk;
        if (more) { ldgA(kb + 1, pa); ldgB(kb + 1, pb); }

        #pragma unroll
        for (int g = 0; g < 4; g++) {
            uint32_t b[8][2];
            #pragma unroll
            for (int ni = 0; ni < 8; ni++) {
                int coln = (wn + ni * 8 + r0) ^ xr;
                b[ni][0] = __float_as_uint(Bsm[buf * 4096 + (g * 8 + c0)     * 128 + coln]);
                b[ni][1] = __float_as_uint(Bsm[buf * 4096 + (g * 8 + c0 + 4) * 128 + coln]);
            }
            #pragma unroll
            for (int mi = 0; mi < 2; mi++) {
                const uint2 lo = *(const uint2*)&Ash[buf * 5120 + (wr + mi * 16 + r0)     * 40 + g * 8 + 2 * c0];
                const uint2 hi = *(const uint2*)&Ash[buf * 5120 + (wr + mi * 16 + 8 + r0) * 40 + g * 8 + 2 * c0];
                uint32_t a[4] = {lo.x, hi.x, lo.y, hi.y};
                #pragma unroll
                for (int ni = 0; ni < 8; ni++) mma_tf32(c[mi][ni], a, b[ni]);
            }
        }

        if (more) {
            const int nbuf = buf ^ 1;
            stsA(nbuf, pa);
            stsB(nbuf, pb);
            __syncthreads();
        }
    }

    // Epilogue
    #pragma unroll
    for (int mi = 0; mi < 2; mi++) {
        #pragma unroll
        for (int ni = 0; ni < 8; ni++) {
            int row = m0 + wr + mi * 16 + r0;
            int col = n0 + wn + ni * 8 + 2 * c0;
            float2 v0, v1;
            v0.x = c[mi][ni][0]; v0.y = c[mi][ni][1];
            v1.x = c[mi][ni][2]; v1.y = c[mi][ni][3];
            if (MODE == 0) {
                // q columns (col < Cc) get softmax scale; all tf32-rounded
                const float sc = (col < Cc) ? SC_Q : 1.0f;
                v0.x = __uint_as_float(f2tf32(v0.x * sc));
                v0.y = __uint_as_float(f2tf32(v0.y * sc));
                v1.x = __uint_as_float(f2tf32(v1.x * sc));
                v1.y = __uint_as_float(f2tf32(v1.y * sc));
            } else {
                float bx = bias[col], by = bias[col + 1];
                v0.x += bx; v0.y += by;
                v1.x += bx; v1.y += by;
            }
            *(float2*)(C + (size_t)row * N + col)       = v0;
            *(float2*)(C + (size_t)(row + 8) * N + col) = v1;
        }
    }
}

// ---------------------------------------------------------------------------
// Tensor-core flash attention (tf32 mma, causal).
// qkv is tf32 with q pre-scaled -> all staging is raw copies.
// Output tf32-rounded (feeds proj GEMM raw).
// ---------------------------------------------------------------------------
#define ATT_SMEM ((2 * 64 * 68 + 8 * 32 * 36) * 4)

__global__ __launch_bounds__(256, 1)
void flash_tc_kernel(const float* __restrict__ qkv, float* __restrict__ out)
{
    extern __shared__ float sm[];
    float* Ksm = sm;                  // [64][68]
    float* Vsm = sm + 64 * 68;        // [64][68]

    const int tid  = threadIdx.x;
    const int lane = tid & 31;
    const int warp = tid >> 5;
    const int r0 = lane >> 2;         // 0..7
    const int c0 = lane & 3;          // 0..3

    float* Phi = sm + 2 * 64 * 68 + warp * (32 * 36);

    const int bh = blockIdx.x;        // 0..63
    const int b  = bh >> 4;
    const int h  = bh & 15;
    const int q0 = (7 - (int)blockIdx.y) * 256;   // heavy blocks first
    const int wr = warp * 32;

    // Q fragments -> registers (already tf32 + scaled)
    uint32_t qa[2][8][4];
    {
        const float* qb = qkv + ((size_t)(b * Tt + q0 + wr)) * NQKV + h * HSd;
        #pragma unroll
        for (int mi = 0; mi < 2; mi++)
            #pragma unroll
            for (int ks = 0; ks < 8; ks++) {
                const float* p0 = qb + (size_t)(mi * 16 + r0)     * NQKV + ks * 8 + c0;
                const float* p1 = qb + (size_t)(mi * 16 + 8 + r0) * NQKV + ks * 8 + c0;
                qa[mi][ks][0] = __float_as_uint(p0[0]);
                qa[mi][ks][1] = __float_as_uint(p1[0]);
                qa[mi][ks][2] = __float_as_uint(p0[4]);
                qa[mi][ks][3] = __float_as_uint(p1[4]);
            }
    }

    float o[2][8][4];
    #pragma unroll
    for (int mi = 0; mi < 2; mi++)
        #pragma unroll
        for (int ni = 0; ni < 8; ni++)
            #pragma unroll
            for (int j = 0; j < 4; j++) o[mi][ni][j] = 0.0f;
    float mrow[4], lrow[4];
    #pragma unroll
    for (int rs = 0; rs < 4; rs++) { mrow[rs] = -1e30f; lrow[rs] = 0.0f; }

    const float* kgb = qkv + ((size_t)b * Tt) * NQKV + Cc + h * HSd;
    const float* vgb = kgb + Cc;

    const int ntiles = q0 / 64 + 4;
    const int firstMaskTile = q0 / 64;

    for (int kt = 0; kt < ntiles; kt++) {
        __syncthreads();
        // Stage K/V tile (raw copies)
        #pragma unroll
        for (int i = 0; i < 4; i++) {
            int idx = i * 256 + tid;
            int row = idx >> 4;
            int cc4 = (idx & 15) << 2;
            *(float4*)&Ksm[row * 68 + cc4] =
                *(const float4*)(kgb + (size_t)(kt * 64 + row) * NQKV + cc4);
            *(float4*)&Vsm[row * 68 + cc4] =
                *(const float4*)(vgb + (size_t)(kt * 64 + row) * NQKV + cc4);
        }
        __syncthreads();

        // S = Q K^T
        float s[2][8][4];
        #pragma unroll
        for (int mi = 0; mi < 2; mi++)
            #pragma unroll
            for (int ni = 0; ni < 8; ni++)
                #pragma unroll
                for (int j = 0; j < 4; j++) s[mi][ni][j] = 0.0f;

        #pragma unroll
        for (int ks = 0; ks < 8; ks++) {
            #pragma unroll
            for (int ni = 0; ni < 8; ni++) {
                uint32_t bb[2];
                bb[0] = __float_as_uint(Ksm[(ni * 8 + r0) * 68 + ks * 8 + c0]);
                bb[1] = __float_as_uint(Ksm[(ni * 8 + r0) * 68 + ks * 8 + c0 + 4]);
                mma_tf32(s[0][ni], qa[0][ks], bb);
                mma_tf32(s[1][ni], qa[1][ks], bb);
            }
        }

        // Causal mask (diagonal tiles only)
        if (kt >= firstMaskTile) {
            #pragma unroll
            for (int mi = 0; mi < 2; mi++) {
                int row = q0 + wr + mi * 16 + r0;
                #pragma unroll
                for (int ni = 0; ni < 8; ni++) {
                    int key = kt * 64 + ni * 8 + 2 * c0;
                    if (key     > row)     s[mi][ni][0] = -1e30f;
                    if (key + 1 > row)     s[mi][ni][1] = -1e30f;
                    if (key     > row + 8) s[mi][ni][2] = -1e30f;
                    if (key + 1 > row + 8) s[mi][ni][3] = -1e30f;
                }
            }
        }

        // Online softmax (exp2 domain); s becomes p
        #pragma unroll
        for (int mi = 0; mi < 2; mi++) {
            #pragma unroll
            for (int h2 = 0; h2 < 2; h2++) {
                const int rs = mi * 2 + h2;
                float mx = -1e30f;
                #pragma unroll
                for (int ni = 0; ni < 8; ni++)
                    mx = fmaxf(mx, fmaxf(s[mi][ni][2 * h2], s[mi][ni][2 * h2 + 1]));
                mx = fmaxf(mx, __shfl_xor_sync(0xffffffffu, mx, 1));
                mx = fmaxf(mx, __shfl_xor_sync(0xffffffffu, mx, 2));
                float mnew = fmaxf(mrow[rs], mx);
                float corr = exp2fast(mrow[rs] - mnew);
                mrow[rs] = mnew;
                float psum = 0.0f;
                #pragma unroll
                for (int ni = 0; ni < 8; ni++) {
                    float p0 = exp2fast(s[mi][ni][2 * h2]     - mnew);
                    float p1 = exp2fast(s[mi][ni][2 * h2 + 1] - mnew);
                    s[mi][ni][2 * h2]     = p0;
                    s[mi][ni][2 * h2 + 1] = p1;
                    psum += p0 + p1;
                }
                lrow[rs] = lrow[rs] * corr + psum;
                #pragma unroll
                for (int ni = 0; ni < 8; ni++) {
                    o[mi][ni][2 * h2]     *= corr;
                    o[mi][ni][2 * h2 + 1] *= corr;
                }
            }
        }

        // O += P V, two 32-key halves (P tf32 via per-warp smem)
        #pragma unroll
        for (int hk = 0; hk < 2; hk++) {
            #pragma unroll
            for (int mi = 0; mi < 2; mi++) {
                #pragma unroll
                for (int h2 = 0; h2 < 2; h2++) {
                    int rloc = mi * 16 + h2 * 8 + r0;
                    #pragma unroll
                    for (int j = 0; j < 4; j++) {
                        float h0 = __uint_as_float(f2tf32(s[mi][hk * 4 + j][2 * h2]));
                        float h1 = __uint_as_float(f2tf32(s[mi][hk * 4 + j][2 * h2 + 1]));
                        *(float2*)&Phi[rloc * 36 + j * 8 + 2 * c0] = make_float2(h0, h1);
                    }
                }
            }
            __syncwarp();
            #pragma unroll
            for (int ks = 0; ks < 4; ks++) {
                uint32_t ah[2][4];
                #pragma unroll
                for (int mi = 0; mi < 2; mi++) {
                    int ra = mi * 16 + r0;
                    ah[mi][0] = __float_as_uint(Phi[ra * 36 + ks * 8 + c0]);
                    ah[mi][1] = __float_as_uint(Phi[(ra + 8) * 36 + ks * 8 + c0]);
                    ah[mi][2] = __float_as_uint(Phi[ra * 36 + ks * 8 + c0 + 4]);
                    ah[mi][3] = __float_as_uint(Phi[(ra + 8) * 36 + ks * 8 + c0 + 4]);
                }
                #pragma unroll
                for (int ni = 0; ni < 8; ni++) {
                    uint32_t bb[2];
                    int vrow = hk * 32 + ks * 8 + c0;
                    bb[0] = __float_as_uint(Vsm[vrow * 68 + ni * 8 + r0]);
                    bb[1] = __float_as_uint(Vsm[(vrow + 4) * 68 + ni * 8 + r0]);
                    mma_tf32(o[0][ni], ah[0], bb);
                    mma_tf32(o[1][ni], ah[1], bb);
                }
            }
            __syncwarp();
        }
    }

    // Final normalize + tf32-round + write
    float linv[4];
    #pragma unroll
    for (int rs = 0; rs < 4; rs++) {
        float l = lrow[rs];
        l += __shfl_xor_sync(0xffffffffu, l, 1);
        l += __shfl_xor_sync(0xffffffffu, l, 2);
        linv[rs] = 1.0f / l;
    }
    float* ob = out + ((size_t)(b * Tt + q0 + wr)) * Cc + h * HSd;
    #pragma unroll
    for (int mi = 0; mi < 2; mi++) {
        #pragma unroll
        for (int h2 = 0; h2 < 2; h2++) {
            int rloc = mi * 16 + h2 * 8 + r0;
            float inv = linv[mi * 2 + h2];
            #pragma unroll
            for (int ni = 0; ni < 8; ni++) {
                float2 v;
                v.x = __uint_as_float(f2tf32(o[mi][ni][2 * h2]     * inv));
                v.y = __uint_as_float(f2tf32(o[mi][ni][2 * h2 + 1] * inv));
                *(float2*)(ob + (size_t)rloc * Cc + ni * 8 + 2 * c0) = v;
            }
        }
    }
}

// ---------------------------------------------------------------------------
extern "C" void kernel_launch(void* const* d_in, const int* in_sizes, int n_in,
                              void* d_out, int out_size)
{
    const float* x     = (const float*)d_in[0];   // [B,T,C]
    const float* Wqkv  = (const float*)d_in[1];   // [C,3C]
    const float* Wproj = (const float*)d_in[2];   // [C,C]
    const float* bproj = (const float*)d_in[3];   // [C]
    float* out = (float*)d_out;                   // [B,T,C]

    float *qkv, *attn, *xc, *wqkvc, *wprojc;
    cudaGetSymbolAddress((void**)&qkv,    g_qkv);
    cudaGetSymbolAddress((void**)&attn,   g_attn);
    cudaGetSymbolAddress((void**)&xc,     g_xc);
    cudaGetSymbolAddress((void**)&wqkvc,  g_wqkv_c);
    cudaGetSymbolAddress((void**)&wprojc, g_wproj_c);

    const int GEMM_SMEM = 18432 * 4;   // 72 KB
    cudaFuncSetAttribute(tgemm_kernel<0>,
                         cudaFuncAttributeMaxDynamicSharedMemorySize, GEMM_SMEM);
    cudaFuncSetAttribute(tgemm_kernel<1>,
                         cudaFuncAttributeMaxDynamicSharedMemorySize, GEMM_SMEM);
    cudaFuncSetAttribute(flash_tc_kernel,
                         cudaFuncAttributeMaxDynamicSharedMemorySize, ATT_SMEM);

    // Prepass: tf32-round x + both weights (elementwise, out-of-loop)
    cvt_kernel<<<(Mm * Cc / 4 + 255) / 256, 256>>>(x, xc, Mm * Cc / 4);
    cvt_kernel<<<(Cc * NQKV / 4 + 255) / 256, 256>>>(Wqkv, wqkvc, Cc * NQKV / 4);
    cvt_kernel<<<(Cc * Cc / 4 + 255) / 256, 256>>>(Wproj, wprojc, Cc * Cc / 4);

    dim3 blk(256);
    // 1) QKV projection: [8192,1024] @ [1024,3072] -> tf32 qkv (q pre-scaled)
    tgemm_kernel<0><<<dim3(NQKV / 128, Mm / 128), blk, GEMM_SMEM>>>(
        xc, wqkvc, nullptr, qkv, Mm, NQKV, Cc);
    // 2) Causal flash attention -> tf32 [B,T,C]
    flash_tc_kernel<<<dim3(Bb * Hh, Tt / 256), blk, ATT_SMEM>>>(qkv, attn);
    // 3) Output projection + bias: [8192,1024] @ [1024,1024]
    tgemm_kernel<1><<<dim3(Cc / 128, Mm / 128), blk, GEMM_SMEM>>>(
        attn, wprojc, bproj, out, Mm, Cc, Cc);
}

// round 10
// speedup vs baseline: 3.6847x; 1.0981x over previous
#include <cuda_runtime.h>
#include <math.h>
#include <stdint.h>

// Problem constants
#define Bb   4
#define Tt   2048
#define Cc   1024
#define Hh   16
#define HSd  64
#define Mm   (Bb * Tt)      // 8192
#define NQKV (3 * Cc)       // 3072

// Scratch (static device globals: allocation rules forbid cudaMalloc)
__device__ float g_qkv[(size_t)Mm * NQKV];     // [B*T, 3C] tf32 (q pre-scaled by SC_Q)
__device__ float g_attn[(size_t)Mm * Cc];      // [B*T, C] tf32 attention out
__device__ float g_xc[(size_t)Mm * Cc];        // x, tf32
__device__ float g_wqkv_c[(size_t)Cc * NQKV];  // W_qkv, tf32, [K][N]
__device__ float g_wproj_c[(size_t)Cc * Cc];   // W_proj, tf32, [K][N]

// ---------------------------------------------------------------------------
// helpers
// ---------------------------------------------------------------------------
static __device__ __forceinline__ uint32_t f2tf32(float x) {
    uint32_t y;
    asm("cvt.rna.tf32.f32 %0, %1;" : "=r"(y) : "f"(x));
    return y;
}

static __device__ __forceinline__ float exp2fast(float x) {
    float y;
    asm("ex2.approx.f32 %0, %1;" : "=f"(y) : "f"(x));
    return y;
}

static __device__ __forceinline__ void mma_tf32(float c[4], const uint32_t a[4],
                                                const uint32_t b[2]) {
    asm volatile(
        "mma.sync.aligned.m16n8k8.row.col.f32.tf32.tf32.f32 "
        "{%0,%1,%2,%3}, {%4,%5,%6,%7}, {%8,%9}, {%0,%1,%2,%3};\n"
        : "+f"(c[0]), "+f"(c[1]), "+f"(c[2]), "+f"(c[3])
        : "r"(a[0]), "r"(a[1]), "r"(a[2]), "r"(a[3]), "r"(b[0]), "r"(b[1]));
}

static __device__ __forceinline__ void cp_async16(uint32_t smem_dst,
                                                  const void* gsrc) {
    asm volatile("cp.async.cg.shared.global [%0], [%1], 16;"
                 :: "r"(smem_dst), "l"(gsrc) : "memory");
}
static __device__ __forceinline__ void cp_async_commit() {
    asm volatile("cp.async.commit_group;" ::: "memory");
}
static __device__ __forceinline__ void cp_async_wait0() {
    asm volatile("cp.async.wait_group 0;" ::: "memory");
}

#define SC_Q (0.125f * 1.4426950408889634f)   // (1/sqrt(64)) * log2(e)

// ---------------------------------------------------------------------------
// Prepass: elementwise tf32-round (vectorized)
// ---------------------------------------------------------------------------
__global__ void cvt_kernel(const float* __restrict__ in, float* __restrict__ out,
                           int n4)
{
    int i = blockIdx.x * blockDim.x + threadIdx.x;
    if (i < n4) {
        float4 v = ((const float4*)in)[i];
        v.x = __uint_as_float(f2tf32(v.x));
        v.y = __uint_as_float(f2tf32(v.y));
        v.z = __uint_as_float(f2tf32(v.z));
        v.w = __uint_as_float(f2tf32(v.w));
        ((float4*)out)[i] = v;
    }
}

// ---------------------------------------------------------------------------
// tf32 tensor-core GEMM: C = A @ B (+ epilogue). Inputs ALREADY tf32-rounded.
// CTA = 128 threads (4 warps, 2x2), CTA tile 128x128, WARP TILE 64x64, BK=16.
// Double-buffered smem; B staged via cp.async (no regs), A via reg prefetch.
// A layout: [row][24], k-pair permutation word(k) = (k>>3)*8+2*(k&3)+((k&7)>>2)
//   -> conflict-free LDS.64 fragments.
// B layout: [k][128], XOR swizzle col ^= 8*(k&3) -> conflict-free LDS.32.
// MODE 0 (QKV): cols < Cc (q) scaled by SC_Q; outputs tf32-rounded.
// MODE 1 (proj): + bias, fp32 out.
// Dyn smem: As(2*128*24) + Bs(2*16*128) floats = 40 KB.
// ---------------------------------------------------------------------------
#define GEMM_SMEM ((2 * 128 * 24 + 2 * 16 * 128) * 4)

template <int MODE>
__global__ __launch_bounds__(128)
void tgemm_kernel(const float* __restrict__ A, const float* __restrict__ B,
                  const float* __restrict__ bias, float* __restrict__ C,
                  int M, int N, int K)
{
    extern __shared__ float smg[];
    float* Ash = smg;               // [2][128*24]
    float* Bsm = smg + 6144;        // [2][16*128]
    const uint32_t sB = (uint32_t)__cvta_generic_to_shared(Bsm);

    const int tid  = threadIdx.x;
    const int lane = tid & 31;
    const int warp = tid >> 5;
    const int m0 = blockIdx.y * 128;
    const int n0 = blockIdx.x * 128;
    const int wr = (warp & 1) * 64;   // warp m offset
    const int wn = (warp >> 1) * 64;  // warp n offset
    const int r0 = lane >> 2;         // 0..7
    const int c0 = lane & 3;          // 0..3
    const int xr = 8 * c0;            // read-side B swizzle

    // Global load assignments (BK=16, 128 threads)
    const int aRow  = tid >> 2;         // 0..31 (+32,+64,+96)
    const int aCol4 = (tid & 3) * 4;    // k offset 0,4,8,12
    const int bKr   = tid >> 5;         // 0..3 (+4,+8,+12)
    const int bN4   = (tid & 31) * 4;   // n offset 0..124
    const int xw    = 8 * (bKr & 3);    // store-side B swizzle (constant per thread)

    float c[4][8][4];
    #pragma unroll
    for (int mi = 0; mi < 4; mi++)
        #pragma unroll
        for (int ni = 0; ni < 8; ni++)
            #pragma unroll
            for (int j = 0; j < 4; j++) c[mi][ni][j] = 0.0f;

    const float* Abase = A + (size_t)m0 * K;
    const float* Bbase = B + n0;
    const int nk = K / 16;

    auto ldgA = [&](int kb, float4 a[4]) {
        #pragma unroll
        for (int i = 0; i < 4; i++)
            a[i] = *(const float4*)(Abase + (size_t)(aRow + i * 32) * K + kb * 16 + aCol4);
    };
    auto stsA = [&](int buf, const float4 a[4]) {
        #pragma unroll
        for (int i = 0; i < 4; i++) {
            float* dst = &Ash[buf * 3072 + (aRow + i * 32) * 24];
            #pragma unroll
            for (int j = 0; j < 4; j++) {
                int k = aCol4 + j;
                int word = ((k >> 3) << 3) + 2 * (k & 3) + ((k & 7) >> 2);
                float x = (j == 0) ? a[i].x : (j == 1) ? a[i].y : (j == 2) ? a[i].z : a[i].w;
                dst[word] = x;
            }
        }
    };
    auto cpB = [&](int kb, int buf) {
        #pragma unroll
        for (int i = 0; i < 4; i++) {
            uint32_t dst = sB + (uint32_t)(buf * 2048 + (bKr + i * 4) * 128 + (bN4 ^ xw)) * 4;
            cp_async16(dst, Bbase + (size_t)(kb * 16 + bKr + i * 4) * N + bN4);
        }
        cp_async_commit();
    };

    // Prologue: stage block 0
    {
        float4 a0[4];
        ldgA(0, a0);
        cpB(0, 0);
        stsA(0, a0);
        cp_async_wait0();
    }
    __syncthreads();

    float4 pa[4];
    for (int kb = 0; kb < nk; kb++) {
        const int buf = kb & 1;
        const bool more = (kb + 1) < nk;
        if (more) {
            cpB(kb + 1, buf ^ 1);      // async B -> other buffer
            ldgA(kb + 1, pa);          // A -> registers
        }

        #pragma unroll
        for (int g = 0; g < 2; g++) {
            uint32_t b[8][2];
            #pragma unroll
            for (int ni = 0; ni < 8; ni++) {
                int coln = (wn + ni * 8 + r0) ^ xr;
                b[ni][0] = __float_as_uint(Bsm[buf * 2048 + (g * 8 + c0)     * 128 + coln]);
                b[ni][1] = __float_as_uint(Bsm[buf * 2048 + (g * 8 + c0 + 4) * 128 + coln]);
            }
            #pragma unroll
            for (int mi = 0; mi < 4; mi++) {
                const uint2 lo = *(const uint2*)&Ash[buf * 3072 + (wr + mi * 16 + r0)     * 24 + g * 8 + 2 * c0];
                const uint2 hi = *(const uint2*)&Ash[buf * 3072 + (wr + mi * 16 + 8 + r0) * 24 + g * 8 + 2 * c0];
                uint32_t a[4] = {lo.x, hi.x, lo.y, hi.y};
                #pragma unroll
                for (int ni = 0; ni < 8; ni++) mma_tf32(c[mi][ni], a, b[ni]);
            }
        }

        if (more) {
            stsA(buf ^ 1, pa);
            cp_async_wait0();
            __syncthreads();
        }
    }

    // Epilogue
    #pragma unroll
    for (int mi = 0; mi < 4; mi++) {
        #pragma unroll
        for (int ni = 0; ni < 8; ni++) {
            int row = m0 + wr + mi * 16 + r0;
            int col = n0 + wn + ni * 8 + 2 * c0;
            float2 v0, v1;
            v0.x = c[mi][ni][0]; v0.y = c[mi][ni][1];
            v1.x = c[mi][ni][2]; v1.y = c[mi][ni][3];
            if (MODE == 0) {
                const float sc = (col < Cc) ? SC_Q : 1.0f;
                v0.x = __uint_as_float(f2tf32(v0.x * sc));
                v0.y = __uint_as_float(f2tf32(v0.y * sc));
                v1.x = __uint_as_float(f2tf32(v1.x * sc));
                v1.y = __uint_as_float(f2tf32(v1.y * sc));
            } else {
                float bx = bias[col], by = bias[col + 1];
                v0.x += bx; v0.y += by;
                v1.x += bx; v1.y += by;
            }
            *(float2*)(C + (size_t)row * N + col)       = v0;
            *(float2*)(C + (size_t)(row + 8) * N + col) = v1;
        }
    }
}

// ---------------------------------------------------------------------------
// Tensor-core flash attention (tf32 mma, causal).
// qkv is tf32 with q pre-scaled -> all staging is raw copies.
// Output tf32-rounded (feeds proj GEMM raw).
// ---------------------------------------------------------------------------
#define ATT_SMEM ((2 * 64 * 68 + 8 * 32 * 36) * 4)

__global__ __launch_bounds__(256, 1)
void flash_tc_kernel(const float* __restrict__ qkv, float* __restrict__ out)
{
    extern __shared__ float sm[];
    float* Ksm = sm;                  // [64][68]
    float* Vsm = sm + 64 * 68;        // [64][68]

    const int tid  = threadIdx.x;
    const int lane = tid & 31;
    const int warp = tid >> 5;
    const int r0 = lane >> 2;         // 0..7
    const int c0 = lane & 3;          // 0..3

    float* Phi = sm + 2 * 64 * 68 + warp * (32 * 36);

    const int bh = blockIdx.x;        // 0..63
    const int b  = bh >> 4;
    const int h  = bh & 15;
    const int q0 = (7 - (int)blockIdx.y) * 256;   // heavy blocks first
    const int wr = warp * 32;

    // Q fragments -> registers (already tf32 + scaled)
    uint32_t qa[2][8][4];
    {
        const float* qb = qkv + ((size_t)(b * Tt + q0 + wr)) * NQKV + h * HSd;
        #pragma unroll
        for (int mi = 0; mi < 2; mi++)
            #pragma unroll
            for (int ks = 0; ks < 8; ks++) {
                const float* p0 = qb + (size_t)(mi * 16 + r0)     * NQKV + ks * 8 + c0;
                const float* p1 = qb + (size_t)(mi * 16 + 8 + r0) * NQKV + ks * 8 + c0;
                qa[mi][ks][0] = __float_as_uint(p0[0]);
                qa[mi][ks][1] = __float_as_uint(p1[0]);
                qa[mi][ks][2] = __float_as_uint(p0[4]);
                qa[mi][ks][3] = __float_as_uint(p1[4]);
            }
    }

    float o[2][8][4];
    #pragma unroll
    for (int mi = 0; mi < 2; mi++)
        #pragma unroll
        for (int ni = 0; ni < 8; ni++)
            #pragma unroll
            for (int j = 0; j < 4; j++) o[mi][ni][j] = 0.0f;
    float mrow[4], lrow[4];
    #pragma unroll
    for (int rs = 0; rs < 4; rs++) { mrow[rs] = -1e30f; lrow[rs] = 0.0f; }

    const float* kgb = qkv + ((size_t)b * Tt) * NQKV + Cc + h * HSd;
    const float* vgb = kgb + Cc;

    const int ntiles = q0 / 64 + 4;
    const int firstMaskTile = q0 / 64;

    for (int kt = 0; kt < ntiles; kt++) {
        __syncthreads();
        // Stage K/V tile (raw copies)
        #pragma unroll
        for (int i = 0; i < 4; i++) {
            int idx = i * 256 + tid;
            int row = idx >> 4;
            int cc4 = (idx & 15) << 2;
            *(float4*)&Ksm[row * 68 + cc4] =
                *(const float4*)(kgb + (size_t)(kt * 64 + row) * NQKV + cc4);
            *(float4*)&Vsm[row * 68 + cc4] =
                *(const float4*)(vgb + (size_t)(kt * 64 + row) * NQKV + cc4);
        }
        __syncthreads();

        // S = Q K^T
        float s[2][8][4];
        #pragma unroll
        for (int mi = 0; mi < 2; mi++)
            #pragma unroll
            for (int ni = 0; ni < 8; ni++)
                #pragma unroll
                for (int j = 0; j < 4; j++) s[mi][ni][j] = 0.0f;

        #pragma unroll
        for (int ks = 0; ks < 8; ks++) {
            #pragma unroll
            for (int ni = 0; ni < 8; ni++) {
                uint32_t bb[2];
                bb[0] = __float_as_uint(Ksm[(ni * 8 + r0) * 68 + ks * 8 + c0]);
                bb[1] = __float_as_uint(Ksm[(ni * 8 + r0) * 68 + ks * 8 + c0 + 4]);
                mma_tf32(s[0][ni], qa[0][ks], bb);
                mma_tf32(s[1][ni], qa[1][ks], bb);
            }
        }

        // Causal mask (diagonal tiles only)
        if (kt >= firstMaskTile) {
            #pragma unroll
            for (int mi = 0; mi < 2; mi++) {
                int row = q0 + wr + mi * 16 + r0;
                #pragma unroll
                for (int ni = 0; ni < 8; ni++) {
                    int key = kt * 64 + ni * 8 + 2 * c0;
                    if (key     > row)     s[mi][ni][0] = -1e30f;
                    if (key + 1 > row)     s[mi][ni][1] = -1e30f;
                    if (key     > row + 8) s[mi][ni][2] = -1e30f;
                    if (key + 1 > row + 8) s[mi][ni][3] = -1e30f;
                }
            }
        }

        // Online softmax (exp2 domain); s becomes p
        #pragma unroll
        for (int mi = 0; mi < 2; mi++) {
            #pragma unroll
            for (int h2 = 0; h2 < 2; h2++) {
                const int rs = mi * 2 + h2;
                float mx = -1e30f;
                #pragma unroll
                for (int ni = 0; ni < 8; ni++)
                    mx = fmaxf(mx, fmaxf(s[mi][ni][2 * h2], s[mi][ni][2 * h2 + 1]));
                mx = fmaxf(mx, __shfl_xor_sync(0xffffffffu, mx, 1));
                mx = fmaxf(mx, __shfl_xor_sync(0xffffffffu, mx, 2));
                float mnew = fmaxf(mrow[rs], mx);
                float corr = exp2fast(mrow[rs] - mnew);
                mrow[rs] = mnew;
                float psum = 0.0f;
                #pragma unroll
                for (int ni = 0; ni < 8; ni++) {
                    float p0 = exp2fast(s[mi][ni][2 * h2]     - mnew);
                    float p1 = exp2fast(s[mi][ni][2 * h2 + 1] - mnew);
                    s[mi][ni][2 * h2]     = p0;
                    s[mi][ni][2 * h2 + 1] = p1;
                    psum += p0 + p1;
                }
                lrow[rs] = lrow[rs] * corr + psum;
                #pragma unroll
                for (int ni = 0; ni < 8; ni++) {
                    o[mi][ni][2 * h2]     *= corr;
                    o[mi][ni][2 * h2 + 1] *= corr;
                }
            }
        }

        // O += P V, two 32-key halves (P tf32 via per-warp smem)
        #pragma unroll
        for (int hk = 0; hk < 2; hk++) {
            #pragma unroll
            for (int mi = 0; mi < 2; mi++) {
                #pragma unroll
                for (int h2 = 0; h2 < 2; h2++) {
                    int rloc = mi * 16 + h2 * 8 + r0;
                    #pragma unroll
                    for (int j = 0; j < 4; j++) {
                        float h0 = __uint_as_float(f2tf32(s[mi][hk * 4 + j][2 * h2]));
                        float h1 = __uint_as_float(f2tf32(s[mi][hk * 4 + j][2 * h2 + 1]));
                        *(float2*)&Phi[rloc * 36 + j * 8 + 2 * c0] = make_float2(h0, h1);
                    }
                }
            }
            __syncwarp();
            #pragma unroll
            for (int ks = 0; ks < 4; ks++) {
                uint32_t ah[2][4];
                #pragma unroll
                for (int mi = 0; mi < 2; mi++) {
                    int ra = mi * 16 + r0;
                    ah[mi][0] = __float_as_uint(Phi[ra * 36 + ks * 8 + c0]);
                    ah[mi][1] = __float_as_uint(Phi[(ra + 8) * 36 + ks * 8 + c0]);
                    ah[mi][2] = __float_as_uint(Phi[ra * 36 + ks * 8 + c0 + 4]);
                    ah[mi][3] = __float_as_uint(Phi[(ra + 8) * 36 + ks * 8 + c0 + 4]);
                }
                #pragma unroll
                for (int ni = 0; ni < 8; ni++) {
                    uint32_t bb[2];
                    int vrow = hk * 32 + ks * 8 + c0;
                    bb[0] = __float_as_uint(Vsm[vrow * 68 + ni * 8 + r0]);
                    bb[1] = __float_as_uint(Vsm[(vrow + 4) * 68 + ni * 8 + r0]);
                    mma_tf32(o[0][ni], ah[0], bb);
                    mma_tf32(o[1][ni], ah[1], bb);
                }
            }
            __syncwarp();
        }
    }

    // Final normalize + tf32-round + write
    float linv[4];
    #pragma unroll
    for (int rs = 0; rs < 4; rs++) {
        float l = lrow[rs];
        l += __shfl_xor_sync(0xffffffffu, l, 1);
        l += __shfl_xor_sync(0xffffffffu, l, 2);
        linv[rs] = 1.0f / l;
    }
    float* ob = out + ((size_t)(b * Tt + q0 + wr)) * Cc + h * HSd;
    #pragma unroll
    for (int mi = 0; mi < 2; mi++) {
        #pragma unroll
        for (int h2 = 0; h2 < 2; h2++) {
            int rloc = mi * 16 + h2 * 8 + r0;
            float inv = linv[mi * 2 + h2];
            #pragma unroll
            for (int ni = 0; ni < 8; ni++) {
                float2 v;
                v.x = __uint_as_float(f2tf32(o[mi][ni][2 * h2]     * inv));
                v.y = __uint_as_float(f2tf32(o[mi][ni][2 * h2 + 1] * inv));
                *(float2*)(ob + (size_t)rloc * Cc + ni * 8 + 2 * c0) = v;
            }
        }
    }
}

// ---------------------------------------------------------------------------
extern "C" void kernel_launch(void* const* d_in, const int* in_sizes, int n_in,
                              void* d_out, int out_size)
{
    const float* x     = (const float*)d_in[0];   // [B,T,C]
    const float* Wqkv  = (const float*)d_in[1];   // [C,3C]
    const float* Wproj = (const float*)d_in[2];   // [C,C]
    const float* bproj = (const float*)d_in[3];   // [C]
    float* out = (float*)d_out;                   // [B,T,C]

    float *qkv, *attn, *xc, *wqkvc, *wprojc;
    cudaGetSymbolAddress((void**)&qkv,    g_qkv);
    cudaGetSymbolAddress((void**)&attn,   g_attn);
    cudaGetSymbolAddress((void**)&xc,     g_xc);
    cudaGetSymbolAddress((void**)&wqkvc,  g_wqkv_c);
    cudaGetSymbolAddress((void**)&wprojc, g_wproj_c);

    cudaFuncSetAttribute(tgemm_kernel<0>,
                         cudaFuncAttributeMaxDynamicSharedMemorySize, GEMM_SMEM);
    cudaFuncSetAttribute(tgemm_kernel<1>,
                         cudaFuncAttributeMaxDynamicSharedMemorySize, GEMM_SMEM);
    cudaFuncSetAttribute(flash_tc_kernel,
                         cudaFuncAttributeMaxDynamicSharedMemorySize, ATT_SMEM);

    // Prepass: tf32-round x + both weights (elementwise, out-of-loop)
    cvt_kernel<<<(Mm * Cc / 4 + 255) / 256, 256>>>(x, xc, Mm * Cc / 4);
    cvt_kernel<<<(Cc * NQKV / 4 + 255) / 256, 256>>>(Wqkv, wqkvc, Cc * NQKV / 4);
    cvt_kernel<<<(Cc * Cc / 4 + 255) / 256, 256>>>(Wproj, wprojc, Cc * Cc / 4);

    // 1) QKV projection: [8192,1024] @ [1024,3072] -> tf32 qkv (q pre-scaled)
    tgemm_kernel<0><<<dim3(NQKV / 128, Mm / 128), 128, GEMM_SMEM>>>(
        xc, wqkvc, nullptr, qkv, Mm, NQKV, Cc);
    // 2) Causal flash attention -> tf32 [B,T,C]
    flash_tc_kernel<<<dim3(Bb * Hh, Tt / 256), 256, ATT_SMEM>>>(qkv, attn);
    // 3) Output projection + bias: [8192,1024] @ [1024,1024]
    tgemm_kernel<1><<<dim3(Cc / 128, Mm / 128), 128, GEMM_SMEM>>>(
        attn, wprojc, bproj, out, Mm, Cc, Cc);
}

// round 11
// speedup vs baseline: 4.3728x; 1.1867x over previous
#include <cuda_runtime.h>
#include <math.h>
#include <stdint.h>

// Problem constants
#define Bb   4
#define Tt   2048
#define Cc   1024
#define Hh   16
#define HSd  64
#define Mm   (Bb * Tt)      // 8192
#define NQKV (3 * Cc)       // 3072

// Scratch (static device globals: allocation rules forbid cudaMalloc)
__device__ float g_qkv[(size_t)Mm * NQKV];     // [B*T, 3C] tf32 (q pre-scaled by SC_Q)
__device__ float g_attn[(size_t)Mm * Cc];      // [B*T, C] tf32 attention out
__device__ float g_xc[(size_t)Mm * Cc];        // x, tf32
__device__ float g_wqkv_c[(size_t)Cc * NQKV];  // W_qkv, tf32, [K][N]
__device__ float g_wproj_c[(size_t)Cc * Cc];   // W_proj, tf32, [K][N]

// ---------------------------------------------------------------------------
// helpers
// ---------------------------------------------------------------------------
static __device__ __forceinline__ uint32_t f2tf32(float x) {
    uint32_t y;
    asm("cvt.rna.tf32.f32 %0, %1;" : "=r"(y) : "f"(x));
    return y;
}

static __device__ __forceinline__ float exp2fast(float x) {
    float y;
    asm("ex2.approx.f32 %0, %1;" : "=f"(y) : "f"(x));
    return y;
}

static __device__ __forceinline__ void mma_tf32(float c[4], const uint32_t a[4],
                                                const uint32_t b[2]) {
    asm volatile(
        "mma.sync.aligned.m16n8k8.row.col.f32.tf32.tf32.f32 "
        "{%0,%1,%2,%3}, {%4,%5,%6,%7}, {%8,%9}, {%0,%1,%2,%3};\n"
        : "+f"(c[0]), "+f"(c[1]), "+f"(c[2]), "+f"(c[3])
        : "r"(a[0]), "r"(a[1]), "r"(a[2]), "r"(a[3]), "r"(b[0]), "r"(b[1]));
}

static __device__ __forceinline__ void cp_async16(uint32_t smem_dst,
                                                  const void* gsrc) {
    asm volatile("cp.async.cg.shared.global [%0], [%1], 16;"
                 :: "r"(smem_dst), "l"(gsrc) : "memory");
}
static __device__ __forceinline__ void cp_async_commit() {
    asm volatile("cp.async.commit_group;" ::: "memory");
}
static __device__ __forceinline__ void cp_async_wait0() {
    asm volatile("cp.async.wait_group 0;" ::: "memory");
}
static __device__ __forceinline__ void cp_async_wait1() {
    asm volatile("cp.async.wait_group 1;" ::: "memory");
}

#define SC_Q (0.125f * 1.4426950408889634f)   // (1/sqrt(64)) * log2(e)

// ---------------------------------------------------------------------------
// Prepass: elementwise tf32-round (vectorized)
// ---------------------------------------------------------------------------
__global__ void cvt_kernel(const float* __restrict__ in, float* __restrict__ out,
                           int n4)
{
    int i = blockIdx.x * blockDim.x + threadIdx.x;
    if (i < n4) {
        float4 v = ((const float4*)in)[i];
        v.x = __uint_as_float(f2tf32(v.x));
        v.y = __uint_as_float(f2tf32(v.y));
        v.z = __uint_as_float(f2tf32(v.z));
        v.w = __uint_as_float(f2tf32(v.w));
        ((float4*)out)[i] = v;
    }
}

// ---------------------------------------------------------------------------
// tf32 tensor-core GEMM: C = A @ B (+ epilogue). Inputs ALREADY tf32-rounded.
// CTA = 128 threads (4 warps, 2x2), CTA tile 128x128, warp tile 64x64, BK=32.
// BOTH operands staged via cp.async (register-lean mainloop -> 3 CTAs/SM).
// 2-stage pipeline, one commit group per k-block, wait_group 1 overlap.
// A smem: [row][32] floats, 16B-chunk swizzle c' = c ^ (row&7)
//   -> fragment LDS.32 conflict-free (bank = ((2g^r0)*4+c0) mod 32).
// B smem: [k][128] floats, chunk swizzle ch' = ch ^ (2*(k&3))
//   -> fragment reads coln ^ 8*c0 conflict-free.
// MODE 0 (QKV): cols < Cc (q) scaled by SC_Q; outputs tf32-rounded.
// MODE 1 (proj): + bias, fp32 out.
// Dyn smem: (2*128*32 + 2*32*128) floats = 64 KB.
// ---------------------------------------------------------------------------
#define GEMM_SMEM (16384 * 4)

template <int MODE>
__global__ __launch_bounds__(128, 3)
void tgemm_kernel(const float* __restrict__ A, const float* __restrict__ B,
                  const float* __restrict__ bias, float* __restrict__ C,
                  int M, int N, int K)
{
    extern __shared__ float smg[];
    const uint32_t sbase = (uint32_t)__cvta_generic_to_shared(smg);

    const int tid  = threadIdx.x;
    const int lane = tid & 31;
    const int warp = tid >> 5;
    const int m0 = blockIdx.y * 128;
    const int n0 = blockIdx.x * 128;
    const int wr = (warp & 1) * 64;   // warp m offset
    const int wn = (warp >> 1) * 64;  // warp n offset
    const int r0 = lane >> 2;         // 0..7
    const int c0 = lane & 3;          // 0..3
    const int xr = 8 * c0;            // read-side B swizzle

    float c[4][8][4];
    #pragma unroll
    for (int mi = 0; mi < 4; mi++)
        #pragma unroll
        for (int ni = 0; ni < 8; ni++)
            #pragma unroll
            for (int j = 0; j < 4; j++) c[mi][ni][j] = 0.0f;

    const float* Abase = A + (size_t)m0 * K;
    const float* Bbase = B + n0;
    const int nk = K / 32;

    // cp.async staging: A = 1024 chunks (128 rows x 8), B = 1024 (32 rows x 32)
    auto cpStage = [&](int kb, int s) {
        #pragma unroll
        for (int i = 0; i < 8; i++) {
            int id  = i * 128 + tid;
            int row = id >> 3;
            int ch  = id & 7;
            uint32_t dst = sbase +
                (uint32_t)(s * 4096 + row * 32 + ((ch ^ (row & 7)) << 2)) * 4;
            cp_async16(dst, Abase + (size_t)row * K + kb * 32 + ch * 4);
        }
        #pragma unroll
        for (int i = 0; i < 8; i++) {
            int id  = i * 128 + tid;
            int row = id >> 5;
            int ch  = id & 31;
            uint32_t dst = sbase +
                (uint32_t)(8192 + s * 4096 + row * 128 + ((ch ^ (2 * (row & 3))) << 2)) * 4;
            cp_async16(dst, Bbase + (size_t)(kb * 32 + row) * N + ch * 4);
        }
        cp_async_commit();
    };

    // Prologue: stage blocks 0 and 1
    cpStage(0, 0);
    cpStage(1, 1);

    for (int kb = 0; kb < nk; kb++) {
        const int buf = kb & 1;
        if (kb + 1 < nk) cp_async_wait1(); else cp_async_wait0();
        __syncthreads();

        const float* As = smg + buf * 4096;
        const float* Bs = smg + 8192 + buf * 4096;
        #pragma unroll
        for (int g = 0; g < 4; g++) {
            uint32_t b[8][2];
            #pragma unroll
            for (int ni = 0; ni < 8; ni++) {
                int coln = (wn + ni * 8 + r0) ^ xr;
                b[ni][0] = __float_as_uint(Bs[(g * 8 + c0)     * 128 + coln]);
                b[ni][1] = __float_as_uint(Bs[(g * 8 + c0 + 4) * 128 + coln]);
            }
            const int sw0 = (((2 * g)     ^ r0) << 2) + c0;
            const int sw1 = (((2 * g + 1) ^ r0) << 2) + c0;
            #pragma unroll
            for (int mi = 0; mi < 4; mi++) {
                const int ra = (wr + mi * 16 + r0) * 32;
                uint32_t a[4];
                a[0] = __float_as_uint(As[ra       + sw0]);
                a[1] = __float_as_uint(As[ra + 256 + sw0]);   // +8 rows
                a[2] = __float_as_uint(As[ra       + sw1]);
                a[3] = __float_as_uint(As[ra + 256 + sw1]);
                #pragma unroll
                for (int ni = 0; ni < 8; ni++) mma_tf32(c[mi][ni], a, b[ni]);
            }
        }

        __syncthreads();
        if (kb + 2 < nk) cpStage(kb + 2, buf);
    }

    // Epilogue
    #pragma unroll
    for (int mi = 0; mi < 4; mi++) {
        #pragma unroll
        for (int ni = 0; ni < 8; ni++) {
            int row = m0 + wr + mi * 16 + r0;
            int col = n0 + wn + ni * 8 + 2 * c0;
            float2 v0, v1;
            v0.x = c[mi][ni][0]; v0.y = c[mi][ni][1];
            v1.x = c[mi][ni][2]; v1.y = c[mi][ni][3];
            if (MODE == 0) {
                const float sc = (col < Cc) ? SC_Q : 1.0f;
                v0.x = __uint_as_float(f2tf32(v0.x * sc));
                v0.y = __uint_as_float(f2tf32(v0.y * sc));
                v1.x = __uint_as_float(f2tf32(v1.x * sc));
                v1.y = __uint_as_float(f2tf32(v1.y * sc));
            } else {
                float bx = bias[col], by = bias[col + 1];
                v0.x += bx; v0.y += by;
                v1.x += bx; v1.y += by;
            }
            *(float2*)(C + (size_t)row * N + col)       = v0;
            *(float2*)(C + (size_t)(row + 8) * N + col) = v1;
        }
    }
}

// ---------------------------------------------------------------------------
// Tensor-core flash attention (tf32 mma, causal).
// qkv is tf32 with q pre-scaled -> all staging is raw copies.
// Output tf32-rounded (feeds proj GEMM raw).
// ---------------------------------------------------------------------------
#define ATT_SMEM ((2 * 64 * 68 + 8 * 32 * 36) * 4)

__global__ __launch_bounds__(256, 1)
void flash_tc_kernel(const float* __restrict__ qkv, float* __restrict__ out)
{
    extern __shared__ float sm[];
    float* Ksm = sm;                  // [64][68]
    float* Vsm = sm + 64 * 68;        // [64][68]

    const int tid  = threadIdx.x;
    const int lane = tid & 31;
    const int warp = tid >> 5;
    const int r0 = lane >> 2;         // 0..7
    const int c0 = lane & 3;          // 0..3

    float* Phi = sm + 2 * 64 * 68 + warp * (32 * 36);

    const int bh = blockIdx.x;        // 0..63
    const int b  = bh >> 4;
    const int h  = bh & 15;
    const int q0 = (7 - (int)blockIdx.y) * 256;   // heavy blocks first
    const int wr = warp * 32;

    // Q fragments -> registers (already tf32 + scaled)
    uint32_t qa[2][8][4];
    {
        const float* qb = qkv + ((size_t)(b * Tt + q0 + wr)) * NQKV + h * HSd;
        #pragma unroll
        for (int mi = 0; mi < 2; mi++)
            #pragma unroll
            for (int ks = 0; ks < 8; ks++) {
                const float* p0 = qb + (size_t)(mi * 16 + r0)     * NQKV + ks * 8 + c0;
                const float* p1 = qb + (size_t)(mi * 16 + 8 + r0) * NQKV + ks * 8 + c0;
                qa[mi][ks][0] = __float_as_uint(p0[0]);
                qa[mi][ks][1] = __float_as_uint(p1[0]);
                qa[mi][ks][2] = __float_as_uint(p0[4]);
                qa[mi][ks][3] = __float_as_uint(p1[4]);
            }
    }

    float o[2][8][4];
    #pragma unroll
    for (int mi = 0; mi < 2; mi++)
        #pragma unroll
        for (int ni = 0; ni < 8; ni++)
            #pragma unroll
            for (int j = 0; j < 4; j++) o[mi][ni][j] = 0.0f;
    float mrow[4], lrow[4];
    #pragma unroll
    for (int rs = 0; rs < 4; rs++) { mrow[rs] = -1e30f; lrow[rs] = 0.0f; }

    const float* kgb = qkv + ((size_t)b * Tt) * NQKV + Cc + h * HSd;
    const float* vgb = kgb + Cc;

    const int ntiles = q0 / 64 + 4;
    const int firstMaskTile = q0 / 64;

    for (int kt = 0; kt < ntiles; kt++) {
        __syncthreads();
        // Stage K/V tile (raw copies)
        #pragma unroll
        for (int i = 0; i < 4; i++) {
            int idx = i * 256 + tid;
            int row = idx >> 4;
            int cc4 = (idx & 15) << 2;
            *(float4*)&Ksm[row * 68 + cc4] =
                *(const float4*)(kgb + (size_t)(kt * 64 + row) * NQKV + cc4);
            *(float4*)&Vsm[row * 68 + cc4] =
                *(const float4*)(vgb + (size_t)(kt * 64 + row) * NQKV + cc4);
        }
        __syncthreads();

        // S = Q K^T
        float s[2][8][4];
        #pragma unroll
        for (int mi = 0; mi < 2; mi++)
            #pragma unroll
            for (int ni = 0; ni < 8; ni++)
                #pragma unroll
                for (int j = 0; j < 4; j++) s[mi][ni][j] = 0.0f;

        #pragma unroll
        for (int ks = 0; ks < 8; ks++) {
            #pragma unroll
            for (int ni = 0; ni < 8; ni++) {
                uint32_t bb[2];
                bb[0] = __float_as_uint(Ksm[(ni * 8 + r0) * 68 + ks * 8 + c0]);
                bb[1] = __float_as_uint(Ksm[(ni * 8 + r0) * 68 + ks * 8 + c0 + 4]);
                mma_tf32(s[0][ni], qa[0][ks], bb);
                mma_tf32(s[1][ni], qa[1][ks], bb);
            }
        }

        // Causal mask (diagonal tiles only)
        if (kt >= firstMaskTile) {
            #pragma unroll
            for (int mi = 0; mi < 2; mi++) {
                int row = q0 + wr + mi * 16 + r0;
                #pragma unroll
                for (int ni = 0; ni < 8; ni++) {
                    int key = kt * 64 + ni * 8 + 2 * c0;
                    if (key     > row)     s[mi][ni][0] = -1e30f;
                    if (key + 1 > row)     s[mi][ni][1] = -1e30f;
                    if (key     > row + 8) s[mi][ni][2] = -1e30f;
                    if (key + 1 > row + 8) s[mi][ni][3] = -1e30f;
                }
            }
        }

        // Online softmax (exp2 domain); s becomes p
        #pragma unroll
        for (int mi = 0; mi < 2; mi++) {
            #pragma unroll
            for (int h2 = 0; h2 < 2; h2++) {
                const int rs = mi * 2 + h2;
                float mx = -1e30f;
                #pragma unroll
                for (int ni = 0; ni < 8; ni++)
                    mx = fmaxf(mx, fmaxf(s[mi][ni][2 * h2], s[mi][ni][2 * h2 + 1]));
                mx = fmaxf(mx, __shfl_xor_sync(0xffffffffu, mx, 1));
                mx = fmaxf(mx, __shfl_xor_sync(0xffffffffu, mx, 2));
                float mnew = fmaxf(mrow[rs], mx);
                float corr = exp2fast(mrow[rs] - mnew);
                mrow[rs] = mnew;
                float psum = 0.0f;
                #pragma unroll
                for (int ni = 0; ni < 8; ni++) {
                    float p0 = exp2fast(s[mi][ni][2 * h2]     - mnew);
                    float p1 = exp2fast(s[mi][ni][2 * h2 + 1] - mnew);
                    s[mi][ni][2 * h2]     = p0;
                    s[mi][ni][2 * h2 + 1] = p1;
                    psum += p0 + p1;
                }
                lrow[rs] = lrow[rs] * corr + psum;
                #pragma unroll
                for (int ni = 0; ni < 8; ni++) {
                    o[mi][ni][2 * h2]     *= corr;
                    o[mi][ni][2 * h2 + 1] *= corr;
                }
            }
        }

        // O += P V, two 32-key halves (P tf32 via per-warp smem)
        #pragma unroll
        for (int hk = 0; hk < 2; hk++) {
            #pragma unroll
            for (int mi = 0; mi < 2; mi++) {
                #pragma unroll
                for (int h2 = 0; h2 < 2; h2++) {
                    int rloc = mi * 16 + h2 * 8 + r0;
                    #pragma unroll
                    for (int j = 0; j < 4; j++) {
                        float h0 = __uint_as_float(f2tf32(s[mi][hk * 4 + j][2 * h2]));
                        float h1 = __uint_as_float(f2tf32(s[mi][hk * 4 + j][2 * h2 + 1]));
                        *(float2*)&Phi[rloc * 36 + j * 8 + 2 * c0] = make_float2(h0, h1);
                    }
                }
            }
            __syncwarp();
            #pragma unroll
            for (int ks = 0; ks < 4; ks++) {
                uint32_t ah[2][4];
                #pragma unroll
                for (int mi = 0; mi < 2; mi++) {
                    int ra = mi * 16 + r0;
                    ah[mi][0] = __float_as_uint(Phi[ra * 36 + ks * 8 + c0]);
                    ah[mi][1] = __float_as_uint(Phi[(ra + 8) * 36 + ks * 8 + c0]);
                    ah[mi][2] = __float_as_uint(Phi[ra * 36 + ks * 8 + c0 + 4]);
                    ah[mi][3] = __float_as_uint(Phi[(ra + 8) * 36 + ks * 8 + c0 + 4]);
                }
                #pragma unroll
                for (int ni = 0; ni < 8; ni++) {
                    uint32_t bb[2];
                    int vrow = hk * 32 + ks * 8 + c0;
                    bb[0] = __float_as_uint(Vsm[vrow * 68 + ni * 8 + r0]);
                    bb[1] = __float_as_uint(Vsm[(vrow + 4) * 68 + ni * 8 + r0]);
                    mma_tf32(o[0][ni], ah[0], bb);
                    mma_tf32(o[1][ni], ah[1], bb);
                }
            }
            __syncwarp();
        }
    }

    // Final normalize + tf32-round + write
    float linv[4];
    #pragma unroll
    for (int rs = 0; rs < 4; rs++) {
        float l = lrow[rs];
        l += __shfl_xor_sync(0xffffffffu, l, 1);
        l += __shfl_xor_sync(0xffffffffu, l, 2);
        linv[rs] = 1.0f / l;
    }
    float* ob = out + ((size_t)(b * Tt + q0 + wr)) * Cc + h * HSd;
    #pragma unroll
    for (int mi = 0; mi < 2; mi++) {
        #pragma unroll
        for (int h2 = 0; h2 < 2; h2++) {
            int rloc = mi * 16 + h2 * 8 + r0;
            float inv = linv[mi * 2 + h2];
            #pragma unroll
            for (int ni = 0; ni < 8; ni++) {
                float2 v;
                v.x = __uint_as_float(f2tf32(o[mi][ni][2 * h2]     * inv));
                v.y = __uint_as_float(f2tf32(o[mi][ni][2 * h2 + 1] * inv));
                *(float2*)(ob + (size_t)rloc * Cc + ni * 8 + 2 * c0) = v;
            }
        }
    }
}

// ---------------------------------------------------------------------------
extern "C" void kernel_launch(void* const* d_in, const int* in_sizes, int n_in,
                              void* d_out, int out_size)
{
    const float* x     = (const float*)d_in[0];   // [B,T,C]
    const float* Wqkv  = (const float*)d_in[1];   // [C,3C]
    const float* Wproj = (const float*)d_in[2];   // [C,C]
    const float* bproj = (const float*)d_in[3];   // [C]
    float* out = (float*)d_out;                   // [B,T,C]

    float *qkv, *attn, *xc, *wqkvc, *wprojc;
    cudaGetSymbolAddress((void**)&qkv,    g_qkv);
    cudaGetSymbolAddress((void**)&attn,   g_attn);
    cudaGetSymbolAddress((void**)&xc,     g_xc);
    cudaGetSymbolAddress((void**)&wqkvc,  g_wqkv_c);
    cudaGetSymbolAddress((void**)&wprojc, g_wproj_c);

    cudaFuncSetAttribute(tgemm_kernel<0>,
                         cudaFuncAttributeMaxDynamicSharedMemorySize, GEMM_SMEM);
    cudaFuncSetAttribute(tgemm_kernel<1>,
                         cudaFuncAttributeMaxDynamicSharedMemorySize, GEMM_SMEM);
    cudaFuncSetAttribute(flash_tc_kernel,
                         cudaFuncAttributeMaxDynamicSharedMemorySize, ATT_SMEM);

    // Prepass: tf32-round x + both weights (elementwise, out-of-loop)
    cvt_kernel<<<(Mm * Cc / 4 + 255) / 256, 256>>>(x, xc, Mm * Cc / 4);
    cvt_kernel<<<(Cc * NQKV / 4 + 255) / 256, 256>>>(Wqkv, wqkvc, Cc * NQKV / 4);
    cvt_kernel<<<(Cc * Cc / 4 + 255) / 256, 256>>>(Wproj, wprojc, Cc * Cc / 4);

    // 1) QKV projection: [8192,1024] @ [1024,3072] -> tf32 qkv (q pre-scaled)
    tgemm_kernel<0><<<dim3(NQKV / 128, Mm / 128), 128, GEMM_SMEM>>>(
        xc, wqkvc, nullptr, qkv, Mm, NQKV, Cc);
    // 2) Causal flash attention -> tf32 [B,T,C]
    flash_tc_kernel<<<dim3(Bb * Hh, Tt / 256), 256, ATT_SMEM>>>(qkv, attn);
    // 3) Output projection + bias: [8192,1024] @ [1024,1024]
    tgemm_kernel<1><<<dim3(Cc / 128, Mm / 128), 128, GEMM_SMEM>>>(
        attn, wprojc, bproj, out, Mm, Cc, Cc);
}

// round 12
// speedup vs baseline: 4.5199x; 1.0336x over previous
#include <cuda_runtime.h>
#include <math.h>
#include <stdint.h>

// Problem constants
#define Bb   4
#define Tt   2048
#define Cc   1024
#define Hh   16
#define HSd  64
#define Mm   (Bb * Tt)      // 8192
#define NQKV (3 * Cc)       // 3072

// Scratch (static device globals: allocation rules forbid cudaMalloc)
__device__ float g_qkv[(size_t)Mm * NQKV];     // [B*T, 3C] tf32 (q pre-scaled by SC_Q)
__device__ float g_attn[(size_t)Mm * Cc];      // [B*T, C] tf32 attention out
__device__ float g_xc[(size_t)Mm * Cc];        // x, tf32
__device__ float g_wqkv_c[(size_t)Cc * NQKV];  // W_qkv, tf32, [K][N]
__device__ float g_wproj_c[(size_t)Cc * Cc];   // W_proj, tf32, [K][N]

// ---------------------------------------------------------------------------
// helpers
// ---------------------------------------------------------------------------
static __device__ __forceinline__ uint32_t f2tf32(float x) {
    uint32_t y;
    asm("cvt.rna.tf32.f32 %0, %1;" : "=r"(y) : "f"(x));
    return y;
}

static __device__ __forceinline__ float exp2fast(float x) {
    float y;
    asm("ex2.approx.f32 %0, %1;" : "=f"(y) : "f"(x));
    return y;
}

static __device__ __forceinline__ void mma_tf32(float c[4], const uint32_t a[4],
                                                const uint32_t b[2]) {
    asm volatile(
        "mma.sync.aligned.m16n8k8.row.col.f32.tf32.tf32.f32 "
        "{%0,%1,%2,%3}, {%4,%5,%6,%7}, {%8,%9}, {%0,%1,%2,%3};\n"
        : "+f"(c[0]), "+f"(c[1]), "+f"(c[2]), "+f"(c[3])
        : "r"(a[0]), "r"(a[1]), "r"(a[2]), "r"(a[3]), "r"(b[0]), "r"(b[1]));
}

static __device__ __forceinline__ void cp_async16(uint32_t smem_dst,
                                                  const void* gsrc) {
    asm volatile("cp.async.cg.shared.global [%0], [%1], 16;"
                 :: "r"(smem_dst), "l"(gsrc) : "memory");
}
static __device__ __forceinline__ void cp_async_commit() {
    asm volatile("cp.async.commit_group;" ::: "memory");
}
static __device__ __forceinline__ void cp_async_wait0() {
    asm volatile("cp.async.wait_group 0;" ::: "memory");
}
static __device__ __forceinline__ void cp_async_wait1() {
    asm volatile("cp.async.wait_group 1;" ::: "memory");
}

#define SC_Q (0.125f * 1.4426950408889634f)   // (1/sqrt(64)) * log2(e)

// ---------------------------------------------------------------------------
// Prepass: elementwise tf32-round (vectorized)
// ---------------------------------------------------------------------------
__global__ void cvt_kernel(const float* __restrict__ in, float* __restrict__ out,
                           int n4)
{
    int i = blockIdx.x * blockDim.x + threadIdx.x;
    if (i < n4) {
        float4 v = ((const float4*)in)[i];
        v.x = __uint_as_float(f2tf32(v.x));
        v.y = __uint_as_float(f2tf32(v.y));
        v.z = __uint_as_float(f2tf32(v.z));
        v.w = __uint_as_float(f2tf32(v.w));
        ((float4*)out)[i] = v;
    }
}

// ---------------------------------------------------------------------------
// tf32 tensor-core GEMM: C = A @ B (+ epilogue). Inputs ALREADY tf32-rounded.
// CTA = 128 threads (4 warps, 2x2), CTA tile 128x128, warp tile 64x64, BK=32.
// BOTH operands staged via cp.async; 2-stage pipeline; 3 CTAs/SM.
// A smem: [row][32], 16B-chunk swizzle c' = c ^ (row&7). B: [k][128],
// chunk swizzle ch' = ch ^ (2*(k&3)). Conflict-free fragment reads.
// MODE 0 (QKV): cols < Cc (q) scaled by SC_Q; outputs tf32-rounded.
// MODE 1 (proj): + bias, fp32 out.
// Dyn smem: 64 KB.
// ---------------------------------------------------------------------------
#define GEMM_SMEM (16384 * 4)

template <int MODE>
__global__ __launch_bounds__(128, 3)
void tgemm_kernel(const float* __restrict__ A, const float* __restrict__ B,
                  const float* __restrict__ bias, float* __restrict__ C,
                  int M, int N, int K)
{
    extern __shared__ float smg[];
    const uint32_t sbase = (uint32_t)__cvta_generic_to_shared(smg);

    const int tid  = threadIdx.x;
    const int lane = tid & 31;
    const int warp = tid >> 5;
    const int m0 = blockIdx.y * 128;
    const int n0 = blockIdx.x * 128;
    const int wr = (warp & 1) * 64;   // warp m offset
    const int wn = (warp >> 1) * 64;  // warp n offset
    const int r0 = lane >> 2;         // 0..7
    const int c0 = lane & 3;          // 0..3
    const int xr = 8 * c0;            // read-side B swizzle

    float c[4][8][4];
    #pragma unroll
    for (int mi = 0; mi < 4; mi++)
        #pragma unroll
        for (int ni = 0; ni < 8; ni++)
            #pragma unroll
            for (int j = 0; j < 4; j++) c[mi][ni][j] = 0.0f;

    const float* Abase = A + (size_t)m0 * K;
    const float* Bbase = B + n0;
    const int nk = K / 32;

    auto cpStage = [&](int kb, int s) {
        #pragma unroll
        for (int i = 0; i < 8; i++) {
            int id  = i * 128 + tid;
            int row = id >> 3;
            int ch  = id & 7;
            uint32_t dst = sbase +
                (uint32_t)(s * 4096 + row * 32 + ((ch ^ (row & 7)) << 2)) * 4;
            cp_async16(dst, Abase + (size_t)row * K + kb * 32 + ch * 4);
        }
        #pragma unroll
        for (int i = 0; i < 8; i++) {
            int id  = i * 128 + tid;
            int row = id >> 5;
            int ch  = id & 31;
            uint32_t dst = sbase +
                (uint32_t)(8192 + s * 4096 + row * 128 + ((ch ^ (2 * (row & 3))) << 2)) * 4;
            cp_async16(dst, Bbase + (size_t)(kb * 32 + row) * N + ch * 4);
        }
        cp_async_commit();
    };

    // Prologue: stage blocks 0 and 1
    cpStage(0, 0);
    cpStage(1, 1);

    for (int kb = 0; kb < nk; kb++) {
        const int buf = kb & 1;
        if (kb + 1 < nk) cp_async_wait1(); else cp_async_wait0();
        __syncthreads();

        const float* As = smg + buf * 4096;
        const float* Bs = smg + 8192 + buf * 4096;
        #pragma unroll
        for (int g = 0; g < 4; g++) {
            uint32_t b[8][2];
            #pragma unroll
            for (int ni = 0; ni < 8; ni++) {
                int coln = (wn + ni * 8 + r0) ^ xr;
                b[ni][0] = __float_as_uint(Bs[(g * 8 + c0)     * 128 + coln]);
                b[ni][1] = __float_as_uint(Bs[(g * 8 + c0 + 4) * 128 + coln]);
            }
            const int sw0 = (((2 * g)     ^ r0) << 2) + c0;
            const int sw1 = (((2 * g + 1) ^ r0) << 2) + c0;
            #pragma unroll
            for (int mi = 0; mi < 4; mi++) {
                const int ra = (wr + mi * 16 + r0) * 32;
                uint32_t a[4];
                a[0] = __float_as_uint(As[ra       + sw0]);
                a[1] = __float_as_uint(As[ra + 256 + sw0]);   // +8 rows
                a[2] = __float_as_uint(As[ra       + sw1]);
                a[3] = __float_as_uint(As[ra + 256 + sw1]);
                #pragma unroll
                for (int ni = 0; ni < 8; ni++) mma_tf32(c[mi][ni], a, b[ni]);
            }
        }

        __syncthreads();
        if (kb + 2 < nk) cpStage(kb + 2, buf);
    }

    // Epilogue
    #pragma unroll
    for (int mi = 0; mi < 4; mi++) {
        #pragma unroll
        for (int ni = 0; ni < 8; ni++) {
            int row = m0 + wr + mi * 16 + r0;
            int col = n0 + wn + ni * 8 + 2 * c0;
            float2 v0, v1;
            v0.x = c[mi][ni][0]; v0.y = c[mi][ni][1];
            v1.x = c[mi][ni][2]; v1.y = c[mi][ni][3];
            if (MODE == 0) {
                const float sc = (col < Cc) ? SC_Q : 1.0f;
                v0.x = __uint_as_float(f2tf32(v0.x * sc));
                v0.y = __uint_as_float(f2tf32(v0.y * sc));
                v1.x = __uint_as_float(f2tf32(v1.x * sc));
                v1.y = __uint_as_float(f2tf32(v1.y * sc));
            } else {
                float bx = bias[col], by = bias[col + 1];
                v0.x += bx; v0.y += by;
                v1.x += bx; v1.y += by;
            }
            *(float2*)(C + (size_t)row * N + col)       = v0;
            *(float2*)(C + (size_t)(row + 8) * N + col) = v1;
        }
    }
}

// ---------------------------------------------------------------------------
// Tensor-core flash attention (tf32 mma, causal).
// cp.async DOUBLE-BUFFERED K/V tiles (64 keys; rows 272B = 17x16B chunks,
// so the conflict-free stride-68 layout is cp.async-compatible unchanged).
// Per-warp causal skip: warp rows end at q0+wr+31 -> skip fully-masked tiles.
// qkv is tf32 with q pre-scaled; output tf32-rounded.
// Smem: 2 x (K[64*68] + V[64*68]) + 8 warps x P[32*36] = 104 KB.
// ---------------------------------------------------------------------------
#define KVF   (64 * 68)                 // floats per K (or V) tile
#define ATT_SMEM ((4 * KVF + 8 * 32 * 36) * 4)

__global__ __launch_bounds__(256, 1)
void flash_tc_kernel(const float* __restrict__ qkv, float* __restrict__ out)
{
    extern __shared__ float sm[];
    const uint32_t sbase = (uint32_t)__cvta_generic_to_shared(sm);

    const int tid  = threadIdx.x;
    const int lane = tid & 31;
    const int warp = tid >> 5;
    const int r0 = lane >> 2;         // 0..7
    const int c0 = lane & 3;          // 0..3

    float* Phi = sm + 4 * KVF + warp * (32 * 36);

    const int bh = blockIdx.x;        // 0..63
    const int b  = bh >> 4;
    const int h  = bh & 15;
    const int q0 = (7 - (int)blockIdx.y) * 256;   // heavy blocks first
    const int wr = warp * 32;

    // Q fragments -> registers (already tf32 + scaled)
    uint32_t qa[2][8][4];
    {
        const float* qb = qkv + ((size_t)(b * Tt + q0 + wr)) * NQKV + h * HSd;
        #pragma unroll
        for (int mi = 0; mi < 2; mi++)
            #pragma unroll
            for (int ks = 0; ks < 8; ks++) {
                const float* p0 = qb + (size_t)(mi * 16 + r0)     * NQKV + ks * 8 + c0;
                const float* p1 = qb + (size_t)(mi * 16 + 8 + r0) * NQKV + ks * 8 + c0;
                qa[mi][ks][0] = __float_as_uint(p0[0]);
                qa[mi][ks][1] = __float_as_uint(p1[0]);
                qa[mi][ks][2] = __float_as_uint(p0[4]);
                qa[mi][ks][3] = __float_as_uint(p1[4]);
            }
    }

    float o[2][8][4];
    #pragma unroll
    for (int mi = 0; mi < 2; mi++)
        #pragma unroll
        for (int ni = 0; ni < 8; ni++)
            #pragma unroll
            for (int j = 0; j < 4; j++) o[mi][ni][j] = 0.0f;
    float mrow[4], lrow[4];
    #pragma unroll
    for (int rs = 0; rs < 4; rs++) { mrow[rs] = -1e30f; lrow[rs] = 0.0f; }

    const float* kgb = qkv + ((size_t)b * Tt) * NQKV + Cc + h * HSd;
    const float* vgb = kgb + Cc;

    const int ntiles = q0 / 64 + 4;
    const int firstMaskTile = (q0 + wr) >> 6;    // per-warp
    const int lastRow = q0 + wr + 31;            // last q-row this warp owns

    // cp.async K/V staging: 64 rows x 17 chunks... 16 chunks of data (64 floats)
    auto cpKV = [&](int kt, int s) {
        const float* kg = kgb + (size_t)(kt * 64) * NQKV;
        const float* vg = vgb + (size_t)(kt * 64) * NQKV;
        #pragma unroll
        for (int i = 0; i < 4; i++) {
            int idx = i * 256 + tid;          // 0..1023
            int row = idx >> 4;
            int cc4 = (idx & 15) << 2;
            uint32_t doff = (uint32_t)(s * 2 * KVF + row * 68 + cc4) * 4;
            cp_async16(sbase + doff,                 kg + (size_t)row * NQKV + cc4);
            cp_async16(sbase + doff + KVF * 4,       vg + (size_t)row * NQKV + cc4);
        }
        cp_async_commit();
    };

    cpKV(0, 0);

    for (int kt = 0; kt < ntiles; kt++) {
        const int buf = kt & 1;
        if (kt + 1 < ntiles) { cpKV(kt + 1, buf ^ 1); cp_async_wait1(); }
        else cp_async_wait0();
        __syncthreads();

        // Per-warp causal skip: tile fully above this warp's diagonal
        if (kt * 64 <= lastRow) {
            const float* Ksm = sm + buf * 2 * KVF;
            const float* Vsm = Ksm + KVF;

            // S = Q K^T
            float s[2][8][4];
            #pragma unroll
            for (int mi = 0; mi < 2; mi++)
                #pragma unroll
                for (int ni = 0; ni < 8; ni++)
                    #pragma unroll
                    for (int j = 0; j < 4; j++) s[mi][ni][j] = 0.0f;

            #pragma unroll
            for (int ks = 0; ks < 8; ks++) {
                #pragma unroll
                for (int ni = 0; ni < 8; ni++) {
                    uint32_t bb[2];
                    bb[0] = __float_as_uint(Ksm[(ni * 8 + r0) * 68 + ks * 8 + c0]);
                    bb[1] = __float_as_uint(Ksm[(ni * 8 + r0) * 68 + ks * 8 + c0 + 4]);
                    mma_tf32(s[0][ni], qa[0][ks], bb);
                    mma_tf32(s[1][ni], qa[1][ks], bb);
                }
            }

            // Causal mask (per-warp diagonal tiles only)
            if (kt >= firstMaskTile) {
                #pragma unroll
                for (int mi = 0; mi < 2; mi++) {
                    int row = q0 + wr + mi * 16 + r0;
                    #pragma unroll
                    for (int ni = 0; ni < 8; ni++) {
                        int key = kt * 64 + ni * 8 + 2 * c0;
                        if (key     > row)     s[mi][ni][0] = -1e30f;
                        if (key + 1 > row)     s[mi][ni][1] = -1e30f;
                        if (key     > row + 8) s[mi][ni][2] = -1e30f;
                        if (key + 1 > row + 8) s[mi][ni][3] = -1e30f;
                    }
                }
            }

            // Online softmax (exp2 domain); s becomes p
            #pragma unroll
            for (int mi = 0; mi < 2; mi++) {
                #pragma unroll
                for (int h2 = 0; h2 < 2; h2++) {
                    const int rs = mi * 2 + h2;
                    float mx = -1e30f;
                    #pragma unroll
                    for (int ni = 0; ni < 8; ni++)
                        mx = fmaxf(mx, fmaxf(s[mi][ni][2 * h2], s[mi][ni][2 * h2 + 1]));
                    mx = fmaxf(mx, __shfl_xor_sync(0xffffffffu, mx, 1));
                    mx = fmaxf(mx, __shfl_xor_sync(0xffffffffu, mx, 2));
                    float mnew = fmaxf(mrow[rs], mx);
                    float corr = exp2fast(mrow[rs] - mnew);
                    mrow[rs] = mnew;
                    float psum = 0.0f;
                    #pragma unroll
                    for (int ni = 0; ni < 8; ni++) {
                        float p0 = exp2fast(s[mi][ni][2 * h2]     - mnew);
                        float p1 = exp2fast(s[mi][ni][2 * h2 + 1] - mnew);
                        s[mi][ni][2 * h2]     = p0;
                        s[mi][ni][2 * h2 + 1] = p1;
                        psum += p0 + p1;
                    }
                    lrow[rs] = lrow[rs] * corr + psum;
                    #pragma unroll
                    for (int ni = 0; ni < 8; ni++) {
                        o[mi][ni][2 * h2]     *= corr;
                        o[mi][ni][2 * h2 + 1] *= corr;
                    }
                }
            }

            // O += P V, two 32-key halves (P tf32 via per-warp smem)
            #pragma unroll
            for (int hk = 0; hk < 2; hk++) {
                #pragma unroll
                for (int mi = 0; mi < 2; mi++) {
                    #pragma unroll
                    for (int h2 = 0; h2 < 2; h2++) {
                        int rloc = mi * 16 + h2 * 8 + r0;
                        #pragma unroll
                        for (int j = 0; j < 4; j++) {
                            float h0 = __uint_as_float(f2tf32(s[mi][hk * 4 + j][2 * h2]));
                            float h1 = __uint_as_float(f2tf32(s[mi][hk * 4 + j][2 * h2 + 1]));
                            *(float2*)&Phi[rloc * 36 + j * 8 + 2 * c0] = make_float2(h0, h1);
                        }
                    }
                }
                __syncwarp();
                #pragma unroll
                for (int ks = 0; ks < 4; ks++) {
                    uint32_t ah[2][4];
                    #pragma unroll
                    for (int mi = 0; mi < 2; mi++) {
                        int ra = mi * 16 + r0;
                        ah[mi][0] = __float_as_uint(Phi[ra * 36 + ks * 8 + c0]);
                        ah[mi][1] = __float_as_uint(Phi[(ra + 8) * 36 + ks * 8 + c0]);
                        ah[mi][2] = __float_as_uint(Phi[ra * 36 + ks * 8 + c0 + 4]);
                        ah[mi][3] = __float_as_uint(Phi[(ra + 8) * 36 + ks * 8 + c0 + 4]);
                    }
                    #pragma unroll
                    for (int ni = 0; ni < 8; ni++) {
                        uint32_t bb[2];
                        int vrow = hk * 32 + ks * 8 + c0;
                        bb[0] = __float_as_uint(Vsm[vrow * 68 + ni * 8 + r0]);
                        bb[1] = __float_as_uint(Vsm[(vrow + 4) * 68 + ni * 8 + r0]);
                        mma_tf32(o[0][ni], ah[0], bb);
                        mma_tf32(o[1][ni], ah[1], bb);
                    }
                }
                __syncwarp();
            }
        }

        __syncthreads();   // all warps done with buf before next prefetch overwrites it
    }

    // Final normalize + tf32-round + write
    float linv[4];
    #pragma unroll
    for (int rs = 0; rs < 4; rs++) {
        float l = lrow[rs];
        l += __shfl_xor_sync(0xffffffffu, l, 1);
        l += __shfl_xor_sync(0xffffffffu, l, 2);
        linv[rs] = 1.0f / l;
    }
    float* ob = out + ((size_t)(b * Tt + q0 + wr)) * Cc + h * HSd;
    #pragma unroll
    for (int mi = 0; mi < 2; mi++) {
        #pragma unroll
        for (int h2 = 0; h2 < 2; h2++) {
            int rloc = mi * 16 + h2 * 8 + r0;
            float inv = linv[mi * 2 + h2];
            #pragma unroll
            for (int ni = 0; ni < 8; ni++) {
                float2 v;
                v.x = __uint_as_float(f2tf32(o[mi][ni][2 * h2]     * inv));
                v.y = __uint_as_float(f2tf32(o[mi][ni][2 * h2 + 1] * inv));
                *(float2*)(ob + (size_t)rloc * Cc + ni * 8 + 2 * c0) = v;
            }
        }
    }
}

// ---------------------------------------------------------------------------
extern "C" void kernel_launch(void* const* d_in, const int* in_sizes, int n_in,
                              void* d_out, int out_size)
{
    const float* x     = (const float*)d_in[0];   // [B,T,C]
    const float* Wqkv  = (const float*)d_in[1];   // [C,3C]
    const float* Wproj = (const float*)d_in[2];   // [C,C]
    const float* bproj = (const float*)d_in[3];   // [C]
    float* out = (float*)d_out;                   // [B,T,C]

    float *qkv, *attn, *xc, *wqkvc, *wprojc;
    cudaGetSymbolAddress((void**)&qkv,    g_qkv);
    cudaGetSymbolAddress((void**)&attn,   g_attn);
    cudaGetSymbolAddress((void**)&xc,     g_xc);
    cudaGetSymbolAddress((void**)&wqkvc,  g_wqkv_c);
    cudaGetSymbolAddress((void**)&wprojc, g_wproj_c);

    cudaFuncSetAttribute(tgemm_kernel<0>,
                         cudaFuncAttributeMaxDynamicSharedMemorySize, GEMM_SMEM);
    cudaFuncSetAttribute(tgemm_kernel<1>,
                         cudaFuncAttributeMaxDynamicSharedMemorySize, GEMM_SMEM);
    cudaFuncSetAttribute(flash_tc_kernel,
                         cudaFuncAttributeMaxDynamicSharedMemorySize, ATT_SMEM);

    // Prepass: tf32-round x + both weights (elementwise, out-of-loop)
    cvt_kernel<<<(Mm * Cc / 4 + 255) / 256, 256>>>(x, xc, Mm * Cc / 4);
    cvt_kernel<<<(Cc * NQKV / 4 + 255) / 256, 256>>>(Wqkv, wqkvc, Cc * NQKV / 4);
    cvt_kernel<<<(Cc * Cc / 4 + 255) / 256, 256>>>(Wproj, wprojc, Cc * Cc / 4);

    // 1) QKV projection: [8192,1024] @ [1024,3072] -> tf32 qkv (q pre-scaled)
    tgemm_kernel<0><<<dim3(NQKV / 128, Mm / 128), 128, GEMM_SMEM>>>(
        xc, wqkvc, nullptr, qkv, Mm, NQKV, Cc);
    // 2) Causal flash attention -> tf32 [B,T,C]
    flash_tc_kernel<<<dim3(Bb * Hh, Tt / 256), 256, ATT_SMEM>>>(qkv, attn);
    // 3) Output projection + bias: [8192,1024] @ [1024,1024]
    tgemm_kernel<1><<<dim3(Cc / 128, Mm / 128), 128, GEMM_SMEM>>>(
        attn, wprojc, bproj, out, Mm, Cc, Cc);
}